// round 4
// baseline (speedup 1.0000x reference)
#include <cuda_runtime.h>
#include <cstdint>
#include <math.h>

#define DIM 128
#define FFN 512
#define KNN 9
#define NMAX 50000
#define TPB 256

typedef unsigned long long ull;

// ---- packed f32x2 helpers (FFMA2 path: 2x fp32 FMA throughput on Blackwell) ----
__device__ __forceinline__ ull ffma2(ull a, ull b, ull c) {
    ull d;
    asm("fma.rn.f32x2 %0, %1, %2, %3;" : "=l"(d) : "l"(a), "l"(b), "l"(c));
    return d;
}
__device__ __forceinline__ ull dup2(float v) {
    unsigned u = __float_as_uint(v);
    ull r;
    asm("mov.b64 %0, {%1, %1};" : "=l"(r) : "r"(u));
    return r;
}
__device__ __forceinline__ float lo2(ull a) {
    unsigned l, h;
    asm("mov.b64 {%0, %1}, %2;" : "=r"(l), "=r"(h) : "l"(a));
    return __uint_as_float(l);
}
__device__ __forceinline__ float hi2(ull a) {
    unsigned l, h;
    asm("mov.b64 {%0, %1}, %2;" : "=r"(l), "=r"(h) : "l"(a));
    return __uint_as_float(h);
}
__device__ __forceinline__ float gelu_exact(float v) {
    return 0.5f * v * (1.0f + erff(v * 0.70710678118654752f));
}

// ---- scratch (static device globals; no allocations anywhere) ----
__device__ float g_h [(size_t)NMAX * DIM];
__device__ float g_x1[(size_t)NMAX * DIM];
__device__ float g_t [(size_t)NMAX * FFN];

// =====================================================================
// Kernel A: h = x @ W_in + b    (M=n, K=128, N=128)
// block: 128 rows total, batches of 32; 64 col-threads x 4 row-groups
// =====================================================================
__global__ __launch_bounds__(TPB) void k_win(const float* __restrict__ x,
        const float* __restrict__ W, const float* __restrict__ b, int n) {
    extern __shared__ float sm[];
    float* Ws = sm;                 // 128*128
    float* xT = Ws + DIM * DIM;     // 128*36 (transposed, padded)
    float* bs = xT + DIM * 36;      // 128
    const int tid = threadIdx.x;
    for (int i = tid; i < DIM * DIM; i += TPB) Ws[i] = W[i];
    if (tid < DIM) bs[tid] = b[tid];
    const int c  = (tid & 63) * 2;
    const int r0 = (tid >> 6) * 8;
    const int row0 = blockIdx.x * 128;
    for (int b0 = row0; b0 < row0 + 128; b0 += 32) {
        __syncthreads();
        for (int i = tid; i < 32 * DIM; i += TPB) {
            int r = i >> 7, k = i & 127;
            int row = b0 + r;
            xT[k * 36 + r] = (row < n) ? x[(size_t)row * DIM + k] : 0.f;
        }
        __syncthreads();
        ull acc[4][2];
        #pragma unroll
        for (int p = 0; p < 4; p++) { acc[p][0] = dup2(bs[c]); acc[p][1] = dup2(bs[c + 1]); }
        #pragma unroll 8
        for (int k = 0; k < DIM; k++) {
            ull wa = dup2(Ws[k * DIM + c]);
            ull wb = dup2(Ws[k * DIM + c + 1]);
            ulonglong2 xA = *(const ulonglong2*)(xT + k * 36 + r0);
            ulonglong2 xB = *(const ulonglong2*)(xT + k * 36 + r0 + 4);
            acc[0][0] = ffma2(xA.x, wa, acc[0][0]); acc[0][1] = ffma2(xA.x, wb, acc[0][1]);
            acc[1][0] = ffma2(xA.y, wa, acc[1][0]); acc[1][1] = ffma2(xA.y, wb, acc[1][1]);
            acc[2][0] = ffma2(xB.x, wa, acc[2][0]); acc[2][1] = ffma2(xB.x, wb, acc[2][1]);
            acc[3][0] = ffma2(xB.y, wa, acc[3][0]); acc[3][1] = ffma2(xB.y, wb, acc[3][1]);
        }
        #pragma unroll
        for (int p = 0; p < 4; p++) {
            int ra = b0 + r0 + 2 * p, rb = ra + 1;
            if (ra < n) *(float2*)&g_h[(size_t)ra * DIM + c] = make_float2(lo2(acc[p][0]), lo2(acc[p][1]));
            if (rb < n) *(float2*)&g_h[(size_t)rb * DIM + c] = make_float2(hi2(acc[p][0]), hi2(acc[p][1]));
        }
    }
}

// =====================================================================
// Kernel B: gather/max-diff + W_upd + W_out + LN1 -> g_x1
// block: 64 rows total, batches of 16
// edge_index dtype auto-detect: reference makes int64, but the harness's
// documented dtype set is {float32,int32,bf16} — it may have downcast to
// int32. Thread 0 probes the first 16 entries interpreted as int64; any
// value outside [0,n) => data is int32. (int32 data misread as int64 has a
// nonzero high word with prob 1-1/n per entry, so false positives are ~0.)
// =====================================================================
__global__ __launch_bounds__(TPB) void k_msg(
        const float* __restrict__ x, const void* __restrict__ eidx,
        const float* __restrict__ Wu, const float* __restrict__ bu,
        const float* __restrict__ Wo, const float* __restrict__ bo,
        const float* __restrict__ g1, const float* __restrict__ b1, int n) {
    extern __shared__ float sm[];
    float* Wus = sm;                   // 256*128
    float* Wos = Wus + 256 * DIM;      // 128*128
    float* hT  = Wos + DIM * DIM;      // 128*20
    float* mdT = hT + DIM * 20;        // 128*20
    float* h2T = mdT + DIM * 20;       // 128*20
    float* bus = h2T + DIM * 20;       // 128
    float* bos = bus + DIM;            // 128
    float* g1s = bos + DIM;            // 128
    float* b1s = g1s + DIM;            // 128
    int*   srcb = (int*)(b1s + DIM);   // 16*9 ints
    int*   flag = srcb + 16 * KNN;     // 1 int: is64
    float* resid = hT;                 // alias: 16*128 <= 128*20
    const int tid = threadIdx.x;
    for (int i = tid; i < 256 * DIM; i += TPB) Wus[i] = Wu[i];
    for (int i = tid; i < DIM * DIM; i += TPB) Wos[i] = Wo[i];
    if (tid < DIM) { bus[tid] = bu[tid]; bos[tid] = bo[tid]; g1s[tid] = g1[tid]; b1s[tid] = b1[tid]; }
    if (tid == 0) {
        const long long* p64 = (const long long*)eidx;
        int ok = 1;
        #pragma unroll
        for (int i = 0; i < 16; i++) {
            long long v = p64[i];
            if (v < 0 || v >= (long long)n) ok = 0;
        }
        *flag = ok;
    }
    const int c  = (tid & 63) * 2;
    const int r0 = (tid >> 6) * 4;
    const int wid = tid >> 5, lane = tid & 31;
    const int row0 = blockIdx.x * 64;
    for (int b0 = row0; b0 < row0 + 64; b0 += 16) {
        __syncthreads();  // publishes flag on first iter; protects hT(resid)/mdT/srcb afterwards
        if (tid < 16 * KNN) {
            int r = tid / KNN, j = tid - r * KNN;
            int row = b0 + r;
            int s = 0;
            if (row < n) {
                size_t e = (size_t)row * KNN + j;
                long long v = (*flag) ? ((const long long*)eidx)[e]
                                      : (long long)((const int*)eidx)[e];
                s = (int)v;
                s = min(max(s, 0), n - 1);
            }
            srcb[tid] = s;
        }
        __syncthreads();
        // gather + elementwise max-diff: md = max_j h[src_j] - h[i]
        for (int i = tid; i < 16 * DIM; i += TPB) {
            int r = i >> 7, d = i & 127;
            int row = b0 + r;
            float hv = 0.f, mdv = 0.f;
            if (row < n) {
                hv = g_h[(size_t)row * DIM + d];
                float m = -3.4e38f;
                #pragma unroll
                for (int j = 0; j < KNN; j++)
                    m = fmaxf(m, g_h[(size_t)srcb[r * KNN + j] * DIM + d]);
                mdv = m - hv;
            }
            hT [d * 20 + r] = hv;
            mdT[d * 20 + r] = mdv;
        }
        __syncthreads();
        // h2 = h @ Wu[0:128] + md @ Wu[128:256] + bu
        ull acc[2][2];
        acc[0][0] = dup2(bus[c]); acc[0][1] = dup2(bus[c + 1]);
        acc[1][0] = acc[0][0];    acc[1][1] = acc[0][1];
        #pragma unroll 8
        for (int k = 0; k < DIM; k++) {
            ull wa = dup2(Wus[k * DIM + c]);
            ull wb = dup2(Wus[k * DIM + c + 1]);
            ulonglong2 xA = *(const ulonglong2*)(hT + k * 20 + r0);
            acc[0][0] = ffma2(xA.x, wa, acc[0][0]); acc[0][1] = ffma2(xA.x, wb, acc[0][1]);
            acc[1][0] = ffma2(xA.y, wa, acc[1][0]); acc[1][1] = ffma2(xA.y, wb, acc[1][1]);
        }
        #pragma unroll 8
        for (int k = 0; k < DIM; k++) {
            ull wa = dup2(Wus[(DIM + k) * DIM + c]);
            ull wb = dup2(Wus[(DIM + k) * DIM + c + 1]);
            ulonglong2 xA = *(const ulonglong2*)(mdT + k * 20 + r0);
            acc[0][0] = ffma2(xA.x, wa, acc[0][0]); acc[0][1] = ffma2(xA.x, wb, acc[0][1]);
            acc[1][0] = ffma2(xA.y, wa, acc[1][0]); acc[1][1] = ffma2(xA.y, wb, acc[1][1]);
        }
        // write h2 transposed
        h2T[ c      * 20 + r0    ] = lo2(acc[0][0]);
        h2T[ c      * 20 + r0 + 1] = hi2(acc[0][0]);
        h2T[ c      * 20 + r0 + 2] = lo2(acc[1][0]);
        h2T[ c      * 20 + r0 + 3] = hi2(acc[1][0]);
        h2T[(c + 1) * 20 + r0    ] = lo2(acc[0][1]);
        h2T[(c + 1) * 20 + r0 + 1] = hi2(acc[0][1]);
        h2T[(c + 1) * 20 + r0 + 2] = lo2(acc[1][1]);
        h2T[(c + 1) * 20 + r0 + 3] = hi2(acc[1][1]);
        __syncthreads();
        // h3 = h2 @ Wo + bo
        acc[0][0] = dup2(bos[c]); acc[0][1] = dup2(bos[c + 1]);
        acc[1][0] = acc[0][0];    acc[1][1] = acc[0][1];
        #pragma unroll 8
        for (int k = 0; k < DIM; k++) {
            ull wa = dup2(Wos[k * DIM + c]);
            ull wb = dup2(Wos[k * DIM + c + 1]);
            ulonglong2 xA = *(const ulonglong2*)(h2T + k * 20 + r0);
            acc[0][0] = ffma2(xA.x, wa, acc[0][0]); acc[0][1] = ffma2(xA.x, wb, acc[0][1]);
            acc[1][0] = ffma2(xA.y, wa, acc[1][0]); acc[1][1] = ffma2(xA.y, wb, acc[1][1]);
        }
        // resid = x + h3  (resid aliases hT; safe: only h2T read above)
        #pragma unroll
        for (int p = 0; p < 2; p++) {
            int rA = r0 + 2 * p, rB = rA + 1;
            if (b0 + rA < n) {
                float2 xv = *(const float2*)&x[(size_t)(b0 + rA) * DIM + c];
                resid[rA * DIM + c    ] = xv.x + lo2(acc[p][0]);
                resid[rA * DIM + c + 1] = xv.y + lo2(acc[p][1]);
            }
            if (b0 + rB < n) {
                float2 xv = *(const float2*)&x[(size_t)(b0 + rB) * DIM + c];
                resid[rB * DIM + c    ] = xv.x + hi2(acc[p][0]);
                resid[rB * DIM + c + 1] = xv.y + hi2(acc[p][1]);
            }
        }
        __syncthreads();
        // LN1: 8 warps x 2 rows
        #pragma unroll
        for (int q = 0; q < 2; q++) {
            int r = wid * 2 + q;
            int row = b0 + r;
            if (row < n) {
                int d = lane * 4;
                float4 v = *(float4*)(resid + r * DIM + d);
                float s  = v.x + v.y + v.z + v.w;
                float sq = v.x * v.x + v.y * v.y + v.z * v.z + v.w * v.w;
                #pragma unroll
                for (int m = 16; m; m >>= 1) {
                    s  += __shfl_xor_sync(0xffffffffu, s,  m);
                    sq += __shfl_xor_sync(0xffffffffu, sq, m);
                }
                float mu = s * (1.f / DIM);
                float var = sq * (1.f / DIM) - mu * mu;
                float rs = rsqrtf(var + 1e-5f);
                float4 o;
                o.x = (v.x - mu) * rs * g1s[d    ] + b1s[d    ];
                o.y = (v.y - mu) * rs * g1s[d + 1] + b1s[d + 1];
                o.z = (v.z - mu) * rs * g1s[d + 2] + b1s[d + 2];
                o.w = (v.w - mu) * rs * g1s[d + 3] + b1s[d + 3];
                *(float4*)&g_x1[(size_t)row * DIM + d] = o;
            }
        }
    }
}

// =====================================================================
// Kernel C: t = gelu(x1 @ ffn1 + b1)   (K=128, N=512 split in 2 col-halves)
// =====================================================================
__global__ __launch_bounds__(TPB) void k_ffn1(const float* __restrict__ W,
        const float* __restrict__ b, int n) {
    extern __shared__ float sm[];
    float* Ws = sm;                 // 128*256
    float* xT = Ws + DIM * 256;     // 128*36
    float* bs = xT + DIM * 36;      // 256
    const int tid = threadIdx.x;
    const int cb = blockIdx.y * 256;
    for (int i = tid; i < DIM * 256; i += TPB) {
        int k = i >> 8, j = i & 255;
        Ws[i] = W[(size_t)k * FFN + cb + j];
    }
    if (tid < 256) bs[tid] = b[cb + tid];
    const int c  = (tid & 127) * 2;
    const int r0 = (tid >> 7) * 16;
    const int row0 = blockIdx.x * 128;
    for (int b0 = row0; b0 < row0 + 128; b0 += 32) {
        __syncthreads();
        for (int i = tid; i < 32 * DIM; i += TPB) {
            int r = i >> 7, k = i & 127;
            int row = b0 + r;
            xT[k * 36 + r] = (row < n) ? g_x1[(size_t)row * DIM + k] : 0.f;
        }
        __syncthreads();
        ull acc[8][2];
        #pragma unroll
        for (int p = 0; p < 8; p++) { acc[p][0] = dup2(bs[c]); acc[p][1] = dup2(bs[c + 1]); }
        #pragma unroll 4
        for (int k = 0; k < DIM; k++) {
            ull wa = dup2(Ws[k * 256 + c]);
            ull wb = dup2(Ws[k * 256 + c + 1]);
            ulonglong2 xA = *(const ulonglong2*)(xT + k * 36 + r0);
            ulonglong2 xB = *(const ulonglong2*)(xT + k * 36 + r0 + 4);
            ulonglong2 xC = *(const ulonglong2*)(xT + k * 36 + r0 + 8);
            ulonglong2 xD = *(const ulonglong2*)(xT + k * 36 + r0 + 12);
            acc[0][0] = ffma2(xA.x, wa, acc[0][0]); acc[0][1] = ffma2(xA.x, wb, acc[0][1]);
            acc[1][0] = ffma2(xA.y, wa, acc[1][0]); acc[1][1] = ffma2(xA.y, wb, acc[1][1]);
            acc[2][0] = ffma2(xB.x, wa, acc[2][0]); acc[2][1] = ffma2(xB.x, wb, acc[2][1]);
            acc[3][0] = ffma2(xB.y, wa, acc[3][0]); acc[3][1] = ffma2(xB.y, wb, acc[3][1]);
            acc[4][0] = ffma2(xC.x, wa, acc[4][0]); acc[4][1] = ffma2(xC.x, wb, acc[4][1]);
            acc[5][0] = ffma2(xC.y, wa, acc[5][0]); acc[5][1] = ffma2(xC.y, wb, acc[5][1]);
            acc[6][0] = ffma2(xD.x, wa, acc[6][0]); acc[6][1] = ffma2(xD.x, wb, acc[6][1]);
            acc[7][0] = ffma2(xD.y, wa, acc[7][0]); acc[7][1] = ffma2(xD.y, wb, acc[7][1]);
        }
        #pragma unroll
        for (int p = 0; p < 8; p++) {
            int ra = b0 + r0 + 2 * p, rb = ra + 1;
            if (ra < n) *(float2*)&g_t[(size_t)ra * FFN + cb + c] =
                make_float2(gelu_exact(lo2(acc[p][0])), gelu_exact(lo2(acc[p][1])));
            if (rb < n) *(float2*)&g_t[(size_t)rb * FFN + cb + c] =
                make_float2(gelu_exact(hi2(acc[p][0])), gelu_exact(hi2(acc[p][1])));
        }
    }
}

// =====================================================================
// Kernel D: f = t @ ffn2 + b2; out = LN2(x1 + f)
// block: 64 rows; K=512 in two smem phases of 256
// =====================================================================
__global__ __launch_bounds__(TPB) void k_ffn2(const float* __restrict__ W,
        const float* __restrict__ b2, const float* __restrict__ g2,
        const float* __restrict__ bl, float* __restrict__ out, int n) {
    extern __shared__ float sm[];
    float* Ws  = sm;                  // 256*128
    float* fp  = Ws + 256 * DIM;      // 64*128
    float* tT  = fp + 64 * DIM;       // 256*36
    float* b2s = tT + 256 * 36;       // 128
    float* g2s = b2s + DIM;           // 128
    float* bls = g2s + DIM;           // 128
    const int tid = threadIdx.x;
    if (tid < DIM) { b2s[tid] = b2[tid]; g2s[tid] = g2[tid]; bls[tid] = bl[tid]; }
    const int c  = (tid & 63) * 2;
    const int r0 = (tid >> 6) * 8;
    const int wid = tid >> 5, lane = tid & 31;
    const int row0 = blockIdx.x * 64;
    for (int ph = 0; ph < 2; ph++) {
        __syncthreads();
        for (int i = tid; i < 256 * DIM; i += TPB)
            Ws[i] = W[(size_t)(ph * 256) * DIM + i];
        __syncthreads();
        for (int bb = 0; bb < 2; bb++) {
            int b0 = row0 + bb * 32;
            for (int i = tid; i < 32 * 256; i += TPB) {
                int r = i >> 8, k = i & 255;
                int row = b0 + r;
                tT[k * 36 + r] = (row < n) ? g_t[(size_t)row * FFN + ph * 256 + k] : 0.f;
            }
            __syncthreads();
            ull acc[4][2];
            #pragma unroll
            for (int p = 0; p < 4; p++) { acc[p][0] = 0ull; acc[p][1] = 0ull; }
            #pragma unroll 8
            for (int k = 0; k < 256; k++) {
                ull wa = dup2(Ws[k * DIM + c]);
                ull wb = dup2(Ws[k * DIM + c + 1]);
                ulonglong2 xA = *(const ulonglong2*)(tT + k * 36 + r0);
                ulonglong2 xB = *(const ulonglong2*)(tT + k * 36 + r0 + 4);
                acc[0][0] = ffma2(xA.x, wa, acc[0][0]); acc[0][1] = ffma2(xA.x, wb, acc[0][1]);
                acc[1][0] = ffma2(xA.y, wa, acc[1][0]); acc[1][1] = ffma2(xA.y, wb, acc[1][1]);
                acc[2][0] = ffma2(xB.x, wa, acc[2][0]); acc[2][1] = ffma2(xB.x, wb, acc[2][1]);
                acc[3][0] = ffma2(xB.y, wa, acc[3][0]); acc[3][1] = ffma2(xB.y, wb, acc[3][1]);
            }
            int rb = bb * 32 + r0;
            if (ph == 0) {
                #pragma unroll
                for (int p = 0; p < 4; p++) {
                    fp[(rb + 2 * p    ) * DIM + c    ] = lo2(acc[p][0]);
                    fp[(rb + 2 * p    ) * DIM + c + 1] = lo2(acc[p][1]);
                    fp[(rb + 2 * p + 1) * DIM + c    ] = hi2(acc[p][0]);
                    fp[(rb + 2 * p + 1) * DIM + c + 1] = hi2(acc[p][1]);
                }
            } else {
                #pragma unroll
                for (int p = 0; p < 4; p++) {
                    fp[(rb + 2 * p    ) * DIM + c    ] += lo2(acc[p][0]);
                    fp[(rb + 2 * p    ) * DIM + c + 1] += lo2(acc[p][1]);
                    fp[(rb + 2 * p + 1) * DIM + c    ] += hi2(acc[p][0]);
                    fp[(rb + 2 * p + 1) * DIM + c + 1] += hi2(acc[p][1]);
                }
            }
            __syncthreads();  // before next tT restage
        }
    }
    // LN2 over 64 rows: 8 warps x 8 rows
    for (int r = wid; r < 64; r += 8) {
        int row = row0 + r;
        if (row >= n) continue;
        int d = lane * 4;
        float4 fv = *(float4*)(fp + r * DIM + d);
        float4 xv = *(const float4*)&g_x1[(size_t)row * DIM + d];
        float4 v;
        v.x = fv.x + xv.x + b2s[d    ];
        v.y = fv.y + xv.y + b2s[d + 1];
        v.z = fv.z + xv.z + b2s[d + 2];
        v.w = fv.w + xv.w + b2s[d + 3];
        float s  = v.x + v.y + v.z + v.w;
        float sq = v.x * v.x + v.y * v.y + v.z * v.z + v.w * v.w;
        #pragma unroll
        for (int m = 16; m; m >>= 1) {
            s  += __shfl_xor_sync(0xffffffffu, s,  m);
            sq += __shfl_xor_sync(0xffffffffu, sq, m);
        }
        float mu = s * (1.f / DIM);
        float var = sq * (1.f / DIM) - mu * mu;
        float rs = rsqrtf(var + 1e-5f);
        float4 o;
        o.x = (v.x - mu) * rs * g2s[d    ] + bls[d    ];
        o.y = (v.y - mu) * rs * g2s[d + 1] + bls[d + 1];
        o.z = (v.z - mu) * rs * g2s[d + 2] + bls[d + 2];
        o.w = (v.w - mu) * rs * g2s[d + 3] + bls[d + 3];
        *(float4*)&out[(size_t)row * DIM + d] = o;
    }
}

// =====================================================================
extern "C" void kernel_launch(void* const* d_in, const int* in_sizes, int n_in,
                              void* d_out, int out_size) {
    const float* x    = (const float*)d_in[0];
    const void*  ei   = (const void*)d_in[1];   // edge_index [2,E]; row 0 = src; dtype auto-detected
    const float* Winw = (const float*)d_in[2];
    const float* Winb = (const float*)d_in[3];
    const float* Wupw = (const float*)d_in[4];
    const float* Wupb = (const float*)d_in[5];
    const float* Wouw = (const float*)d_in[6];
    const float* Woub = (const float*)d_in[7];
    const float* ln1g = (const float*)d_in[8];
    const float* ln1b = (const float*)d_in[9];
    const float* ln2g = (const float*)d_in[10];
    const float* ln2b = (const float*)d_in[11];
    const float* f1w  = (const float*)d_in[12];
    const float* f1b  = (const float*)d_in[13];
    const float* f2w  = (const float*)d_in[14];
    const float* f2b  = (const float*)d_in[15];
    float* out = (float*)d_out;

    const int n = in_sizes[0] / DIM;

    const int SMEM_A = (DIM * DIM + DIM * 36 + DIM) * 4;
    const int SMEM_B = (256 * DIM + DIM * DIM + 3 * DIM * 20 + 4 * DIM) * 4 + (16 * KNN + 1) * 4;
    const int SMEM_C = (DIM * 256 + DIM * 36 + 256) * 4;
    const int SMEM_D = (256 * DIM + 64 * DIM + 256 * 36 + 3 * DIM) * 4;

    cudaFuncSetAttribute(k_win,  cudaFuncAttributeMaxDynamicSharedMemorySize, SMEM_A);
    cudaFuncSetAttribute(k_msg,  cudaFuncAttributeMaxDynamicSharedMemorySize, SMEM_B);
    cudaFuncSetAttribute(k_ffn1, cudaFuncAttributeMaxDynamicSharedMemorySize, SMEM_C);
    cudaFuncSetAttribute(k_ffn2, cudaFuncAttributeMaxDynamicSharedMemorySize, SMEM_D);

    dim3 ga((n + 127) / 128);
    dim3 gb((n + 63) / 64);
    dim3 gc((n + 127) / 128, 2);
    dim3 gd((n + 63) / 64);

    k_win <<<ga, TPB, SMEM_A>>>(x, Winw, Winb, n);
    k_msg <<<gb, TPB, SMEM_B>>>(x, ei, Wupw, Wupb, Wouw, Woub, ln1g, ln1b, n);
    k_ffn1<<<gc, TPB, SMEM_C>>>(f1w, f1b, n);
    k_ffn2<<<gd, TPB, SMEM_D>>>(f2w, f2b, ln2g, ln2b, out, n);
}

// round 5
// speedup vs baseline: 1.0972x; 1.0972x over previous
#include <cuda_runtime.h>
#include <cstdint>
#include <math.h>

#define DIM 128
#define FFN 512
#define KNN 9
#define NMAX 50000
#define TPB 512

typedef unsigned long long ull;

// ---- packed f32x2 helpers ----
__device__ __forceinline__ ull ffma2(ull a, ull b, ull c) {
    ull d;
    asm("fma.rn.f32x2 %0, %1, %2, %3;" : "=l"(d) : "l"(a), "l"(b), "l"(c));
    return d;
}
__device__ __forceinline__ ull dup2(float v) {
    unsigned u = __float_as_uint(v);
    ull r;
    asm("mov.b64 %0, {%1, %1};" : "=l"(r) : "r"(u));
    return r;
}
__device__ __forceinline__ float lo2(ull a) {
    unsigned l, h;
    asm("mov.b64 {%0, %1}, %2;" : "=r"(l), "=r"(h) : "l"(a));
    return __uint_as_float(l);
}
__device__ __forceinline__ float hi2(ull a) {
    unsigned l, h;
    asm("mov.b64 {%0, %1}, %2;" : "=r"(l), "=r"(h) : "l"(a));
    return __uint_as_float(h);
}
__device__ __forceinline__ float gelu_exact(float v) {
    return 0.5f * v * (1.0f + erff(v * 0.70710678118654752f));
}

// ---- scratch (static device globals; no allocations anywhere) ----
__device__ float g_h [(size_t)NMAX * DIM];
__device__ float g_h2[(size_t)NMAX * DIM];
__device__ float g_x1[(size_t)NMAX * DIM];
__device__ float g_t [(size_t)NMAX * FFN];

// Inner 8-row x 2-col packed MMA step (w = ((wa,wa),(wb,wb)))
#define MM8(w, xA, xB)                                          \
    a00 = ffma2(xA.x, w.x, a00); a01 = ffma2(xA.x, w.y, a01);   \
    a10 = ffma2(xA.y, w.x, a10); a11 = ffma2(xA.y, w.y, a11);   \
    a20 = ffma2(xB.x, w.x, a20); a21 = ffma2(xB.x, w.y, a21);   \
    a30 = ffma2(xB.y, w.x, a30); a31 = ffma2(xB.y, w.y, a31);

// =====================================================================
// Kernel A: h = x @ W_in + b   (K=128, 128 cols; 128 rows/block, 2x64)
// Weights pre-duplicated in smem: Wd[k][j*4] = {w[2j],w[2j],w[2j+1],w[2j+1]}
// =====================================================================
__global__ __launch_bounds__(TPB) void k_win(const float* __restrict__ x,
        const float* __restrict__ W, const float* __restrict__ b, int n) {
    extern __shared__ float sm[];
    float* Wd = sm;               // 128*256
    float* xT = Wd + DIM * 256;   // 128*68
    const int tid = threadIdx.x;
    const int cg = tid & 63;
    const int r0 = (tid >> 6) * 8;
    for (int i = tid; i < DIM * 64; i += TPB) {
        int k = i >> 6, j = i & 63;
        float2 w = *(const float2*)(W + (size_t)k * DIM + 2 * j);
        *(float4*)(Wd + k * 256 + j * 4) = make_float4(w.x, w.x, w.y, w.y);
    }
    float2 bv = *(const float2*)(b + 2 * cg);
    const ull ba = dup2(bv.x), bb = dup2(bv.y);
    const int row0 = blockIdx.x * 128;
    const float* wp = Wd + cg * 4;
    const float* xp = xT + r0;
    const int c = cg * 2;
    for (int bb0 = 0; bb0 < 2; bb0++) {
        int b0 = row0 + bb0 * 64;
        __syncthreads();
        for (int i = tid; i < 64 * DIM; i += TPB) {
            int r = i >> 7, k = i & 127;
            int row = b0 + r;
            xT[k * 68 + r] = (row < n) ? x[(size_t)row * DIM + k] : 0.f;
        }
        __syncthreads();
        ull a00 = ba, a01 = bb, a10 = ba, a11 = bb, a20 = ba, a21 = bb, a30 = ba, a31 = bb;
        #pragma unroll 8
        for (int k = 0; k < DIM; k++) {
            ulonglong2 w  = *(const ulonglong2*)(wp + k * 256);
            ulonglong2 xA = *(const ulonglong2*)(xp + k * 68);
            ulonglong2 xB = *(const ulonglong2*)(xp + k * 68 + 4);
            MM8(w, xA, xB)
        }
        int r = b0 + r0;
        if (r     < n) *(float2*)&g_h[(size_t)(r    ) * DIM + c] = make_float2(lo2(a00), lo2(a01));
        if (r + 1 < n) *(float2*)&g_h[(size_t)(r + 1) * DIM + c] = make_float2(hi2(a00), hi2(a01));
        if (r + 2 < n) *(float2*)&g_h[(size_t)(r + 2) * DIM + c] = make_float2(lo2(a10), lo2(a11));
        if (r + 3 < n) *(float2*)&g_h[(size_t)(r + 3) * DIM + c] = make_float2(hi2(a10), hi2(a11));
        if (r + 4 < n) *(float2*)&g_h[(size_t)(r + 4) * DIM + c] = make_float2(lo2(a20), lo2(a21));
        if (r + 5 < n) *(float2*)&g_h[(size_t)(r + 5) * DIM + c] = make_float2(hi2(a20), hi2(a21));
        if (r + 6 < n) *(float2*)&g_h[(size_t)(r + 6) * DIM + c] = make_float2(lo2(a30), lo2(a31));
        if (r + 7 < n) *(float2*)&g_h[(size_t)(r + 7) * DIM + c] = make_float2(hi2(a30), hi2(a31));
    }
}

// =====================================================================
// Kernel B1: gather + max-diff + concat GEMM (Wu, K=256 in 2 phases)
// 32 rows/block; h2 -> g_h2.  edge_index dtype auto-detected (int64/int32).
// =====================================================================
__global__ __launch_bounds__(TPB) void k_msg1(const void* __restrict__ eidx,
        const float* __restrict__ Wu, const float* __restrict__ bu, int n) {
    extern __shared__ float sm[];
    float* Wd  = sm;                    // 128*256
    float* hT  = Wd + DIM * 256;        // 128*36
    float* mdT = hT + DIM * 36;         // 128*36
    int*   srcb = (int*)(mdT + DIM * 36); // 32*9
    int*   flag = srcb + 32 * KNN;
    const int tid = threadIdx.x;
    const int cg = tid & 63;
    const int r0 = (tid >> 6) * 4;
    const int row0 = blockIdx.x * 32;
    if (tid == 0) {
        const long long* p64 = (const long long*)eidx;
        int ok = 1;
        #pragma unroll
        for (int i = 0; i < 16; i++) {
            long long v = p64[i];
            if (v < 0 || v >= (long long)n) ok = 0;
        }
        *flag = ok;
    }
    __syncthreads();
    if (tid < 32 * KNN) {
        int r = tid / KNN, j = tid - r * KNN;
        int row = row0 + r;
        int s = 0;
        if (row < n) {
            size_t e = (size_t)row * KNN + j;
            long long v = (*flag) ? ((const long long*)eidx)[e]
                                  : (long long)((const int*)eidx)[e];
            s = (int)v;
            s = min(max(s, 0), n - 1);
        }
        srcb[tid] = s;
    }
    // phase-0 weights while waiting
    for (int i = tid; i < DIM * 64; i += TPB) {
        int k = i >> 6, j = i & 63;
        float2 w = *(const float2*)(Wu + (size_t)k * DIM + 2 * j);
        *(float4*)(Wd + k * 256 + j * 4) = make_float4(w.x, w.x, w.y, w.y);
    }
    __syncthreads();
    // gather + max-diff
    for (int i = tid; i < 32 * DIM; i += TPB) {
        int r = i >> 7, d = i & 127;
        int row = row0 + r;
        float hv = 0.f, mdv = 0.f;
        if (row < n) {
            hv = g_h[(size_t)row * DIM + d];
            float m = -3.4e38f;
            #pragma unroll
            for (int j = 0; j < KNN; j++)
                m = fmaxf(m, g_h[(size_t)srcb[r * KNN + j] * DIM + d]);
            mdv = m - hv;
        }
        hT [d * 36 + r] = hv;
        mdT[d * 36 + r] = mdv;
    }
    __syncthreads();
    float2 bv = *(const float2*)(bu + 2 * cg);
    ull a00 = dup2(bv.x), a01 = dup2(bv.y), a10 = a00, a11 = a01;
    const float* wp = Wd + cg * 4;
    // GEMM phase 0: h part
    #pragma unroll 8
    for (int k = 0; k < DIM; k++) {
        ulonglong2 w  = *(const ulonglong2*)(wp + k * 256);
        ulonglong2 xA = *(const ulonglong2*)(hT + k * 36 + r0);
        a00 = ffma2(xA.x, w.x, a00); a01 = ffma2(xA.x, w.y, a01);
        a10 = ffma2(xA.y, w.x, a10); a11 = ffma2(xA.y, w.y, a11);
    }
    __syncthreads();
    // phase-1 weights (Wu rows 128..255)
    for (int i = tid; i < DIM * 64; i += TPB) {
        int k = i >> 6, j = i & 63;
        float2 w = *(const float2*)(Wu + (size_t)(DIM + k) * DIM + 2 * j);
        *(float4*)(Wd + k * 256 + j * 4) = make_float4(w.x, w.x, w.y, w.y);
    }
    __syncthreads();
    // GEMM phase 1: max-diff part
    #pragma unroll 8
    for (int k = 0; k < DIM; k++) {
        ulonglong2 w  = *(const ulonglong2*)(wp + k * 256);
        ulonglong2 xA = *(const ulonglong2*)(mdT + k * 36 + r0);
        a00 = ffma2(xA.x, w.x, a00); a01 = ffma2(xA.x, w.y, a01);
        a10 = ffma2(xA.y, w.x, a10); a11 = ffma2(xA.y, w.y, a11);
    }
    const int c = cg * 2;
    int r = row0 + r0;
    if (r     < n) *(float2*)&g_h2[(size_t)(r    ) * DIM + c] = make_float2(lo2(a00), lo2(a01));
    if (r + 1 < n) *(float2*)&g_h2[(size_t)(r + 1) * DIM + c] = make_float2(hi2(a00), hi2(a01));
    if (r + 2 < n) *(float2*)&g_h2[(size_t)(r + 2) * DIM + c] = make_float2(lo2(a10), lo2(a11));
    if (r + 3 < n) *(float2*)&g_h2[(size_t)(r + 3) * DIM + c] = make_float2(hi2(a10), hi2(a11));
}

// =====================================================================
// Kernel B2: h3 = h2 @ Wo + bo; x1 = LN1(x + h3) -> g_x1  (64 rows/block)
// =====================================================================
__global__ __launch_bounds__(TPB) void k_msg2(const float* __restrict__ x,
        const float* __restrict__ Wo, const float* __restrict__ bo,
        const float* __restrict__ g1, const float* __restrict__ b1, int n) {
    extern __shared__ float sm[];
    float* Wd  = sm;               // 128*256
    float* h2T = Wd + DIM * 256;   // 128*68 ; reused as resid (64*128) after GEMM
    const int tid = threadIdx.x;
    const int cg = tid & 63;
    const int r0 = (tid >> 6) * 8;
    const int wid = tid >> 5, lane = tid & 31;
    const int row0 = blockIdx.x * 64;
    for (int i = tid; i < DIM * 64; i += TPB) {
        int k = i >> 6, j = i & 63;
        float2 w = *(const float2*)(Wo + (size_t)k * DIM + 2 * j);
        *(float4*)(Wd + k * 256 + j * 4) = make_float4(w.x, w.x, w.y, w.y);
    }
    for (int i = tid; i < 64 * DIM; i += TPB) {
        int r = i >> 7, k = i & 127;
        int row = row0 + r;
        h2T[k * 68 + r] = (row < n) ? g_h2[(size_t)row * DIM + k] : 0.f;
    }
    __syncthreads();
    float2 bv = *(const float2*)(bo + 2 * cg);
    ull a00 = dup2(bv.x), a01 = dup2(bv.y);
    ull a10 = a00, a11 = a01, a20 = a00, a21 = a01, a30 = a00, a31 = a01;
    const float* wp = Wd + cg * 4;
    const float* xp = h2T + r0;
    #pragma unroll 8
    for (int k = 0; k < DIM; k++) {
        ulonglong2 w  = *(const ulonglong2*)(wp + k * 256);
        ulonglong2 xA = *(const ulonglong2*)(xp + k * 68);
        ulonglong2 xB = *(const ulonglong2*)(xp + k * 68 + 4);
        MM8(w, xA, xB)
    }
    __syncthreads();   // everyone done reading h2T; reuse as resid
    float* resid = h2T;
    const int c = cg * 2;
    {
        float v[8][2] = {
            {lo2(a00), lo2(a01)}, {hi2(a00), hi2(a01)},
            {lo2(a10), lo2(a11)}, {hi2(a10), hi2(a11)},
            {lo2(a20), lo2(a21)}, {hi2(a20), hi2(a21)},
            {lo2(a30), lo2(a31)}, {hi2(a30), hi2(a31)}};
        #pragma unroll
        for (int p = 0; p < 8; p++) {
            int row = row0 + r0 + p;
            if (row < n) {
                float2 xv = *(const float2*)&x[(size_t)row * DIM + c];
                resid[(r0 + p) * DIM + c    ] = xv.x + v[p][0];
                resid[(r0 + p) * DIM + c + 1] = xv.y + v[p][1];
            }
        }
    }
    __syncthreads();
    // LN1: 16 warps x 4 rows
    #pragma unroll
    for (int q = 0; q < 4; q++) {
        int rl = wid * 4 + q;
        int row = row0 + rl;
        if (row >= n) continue;
        int d = lane * 4;
        float4 v = *(float4*)(resid + rl * DIM + d);
        float s  = v.x + v.y + v.z + v.w;
        float sq = v.x * v.x + v.y * v.y + v.z * v.z + v.w * v.w;
        #pragma unroll
        for (int m = 16; m; m >>= 1) {
            s  += __shfl_xor_sync(0xffffffffu, s,  m);
            sq += __shfl_xor_sync(0xffffffffu, sq, m);
        }
        float mu = s * (1.f / DIM);
        float var = sq * (1.f / DIM) - mu * mu;
        float rs = rsqrtf(var + 1e-5f);
        float4 gv = *(const float4*)(g1 + d);
        float4 bl = *(const float4*)(b1 + d);
        float4 o;
        o.x = (v.x - mu) * rs * gv.x + bl.x;
        o.y = (v.y - mu) * rs * gv.y + bl.y;
        o.z = (v.z - mu) * rs * gv.z + bl.z;
        o.w = (v.w - mu) * rs * gv.w + bl.w;
        *(float4*)&g_x1[(size_t)row * DIM + d] = o;
    }
}

// =====================================================================
// Kernel C: t = gelu(x1 @ ffn1 + b)  (grid.y=4 col-slices of 128)
// =====================================================================
__global__ __launch_bounds__(TPB) void k_ffn1(const float* __restrict__ W,
        const float* __restrict__ b, int n) {
    extern __shared__ float sm[];
    float* Wd = sm;               // 128*256
    float* xT = Wd + DIM * 256;   // 128*68
    const int tid = threadIdx.x;
    const int cg = tid & 63;
    const int r0 = (tid >> 6) * 8;
    const int colbase = blockIdx.y * 128;
    for (int i = tid; i < DIM * 64; i += TPB) {
        int k = i >> 6, j = i & 63;
        float2 w = *(const float2*)(W + (size_t)k * FFN + colbase + 2 * j);
        *(float4*)(Wd + k * 256 + j * 4) = make_float4(w.x, w.x, w.y, w.y);
    }
    float2 bv = *(const float2*)(b + colbase + 2 * cg);
    const ull ba = dup2(bv.x), bb = dup2(bv.y);
    const int row0 = blockIdx.x * 128;
    const float* wp = Wd + cg * 4;
    const float* xp = xT + r0;
    const int c = colbase + cg * 2;
    for (int bb0 = 0; bb0 < 2; bb0++) {
        int b0 = row0 + bb0 * 64;
        __syncthreads();
        for (int i = tid; i < 64 * DIM; i += TPB) {
            int r = i >> 7, k = i & 127;
            int row = b0 + r;
            xT[k * 68 + r] = (row < n) ? g_x1[(size_t)row * DIM + k] : 0.f;
        }
        __syncthreads();
        ull a00 = ba, a01 = bb, a10 = ba, a11 = bb, a20 = ba, a21 = bb, a30 = ba, a31 = bb;
        #pragma unroll 8
        for (int k = 0; k < DIM; k++) {
            ulonglong2 w  = *(const ulonglong2*)(wp + k * 256);
            ulonglong2 xA = *(const ulonglong2*)(xp + k * 68);
            ulonglong2 xB = *(const ulonglong2*)(xp + k * 68 + 4);
            MM8(w, xA, xB)
        }
        float v[8][2] = {
            {lo2(a00), lo2(a01)}, {hi2(a00), hi2(a01)},
            {lo2(a10), lo2(a11)}, {hi2(a10), hi2(a11)},
            {lo2(a20), lo2(a21)}, {hi2(a20), hi2(a21)},
            {lo2(a30), lo2(a31)}, {hi2(a30), hi2(a31)}};
        #pragma unroll
        for (int p = 0; p < 8; p++) {
            int row = b0 + r0 + p;
            if (row < n)
                *(float2*)&g_t[(size_t)row * FFN + c] =
                    make_float2(gelu_exact(v[p][0]), gelu_exact(v[p][1]));
        }
    }
}

// =====================================================================
// Kernel D: f = t @ ffn2 + b2; out = LN2(x1 + f)
// 64 rows/block, K=512 in 4 phases, acc in regs; fused LN2.
// =====================================================================
__global__ __launch_bounds__(TPB) void k_ffn2(const float* __restrict__ W,
        const float* __restrict__ b2, const float* __restrict__ g2,
        const float* __restrict__ bl, float* __restrict__ out, int n) {
    extern __shared__ float sm[];
    float* Wd = sm;               // 128*256
    float* tT = Wd + DIM * 256;   // 128*68 ; reused as resid (64*128)
    const int tid = threadIdx.x;
    const int cg = tid & 63;
    const int r0 = (tid >> 6) * 8;
    const int wid = tid >> 5, lane = tid & 31;
    const int row0 = blockIdx.x * 64;
    float2 bv = *(const float2*)(b2 + 2 * cg);
    ull a00 = dup2(bv.x), a01 = dup2(bv.y);
    ull a10 = a00, a11 = a01, a20 = a00, a21 = a01, a30 = a00, a31 = a01;
    const float* wp = Wd + cg * 4;
    const float* xp = tT + r0;
    for (int ph = 0; ph < 4; ph++) {
        __syncthreads();
        for (int i = tid; i < DIM * 64; i += TPB) {
            int k = i >> 6, j = i & 63;
            float2 w = *(const float2*)(W + (size_t)(ph * 128 + k) * DIM + 2 * j);
            *(float4*)(Wd + k * 256 + j * 4) = make_float4(w.x, w.x, w.y, w.y);
        }
        for (int i = tid; i < 64 * DIM; i += TPB) {
            int r = i >> 7, k = i & 127;
            int row = row0 + r;
            tT[k * 68 + r] = (row < n) ? g_t[(size_t)row * FFN + ph * 128 + k] : 0.f;
        }
        __syncthreads();
        #pragma unroll 8
        for (int k = 0; k < DIM; k++) {
            ulonglong2 w  = *(const ulonglong2*)(wp + k * 256);
            ulonglong2 xA = *(const ulonglong2*)(xp + k * 68);
            ulonglong2 xB = *(const ulonglong2*)(xp + k * 68 + 4);
            MM8(w, xA, xB)
        }
    }
    __syncthreads();   // all GEMM reads done; reuse tT as resid
    float* resid = tT;
    const int c = cg * 2;
    {
        float v[8][2] = {
            {lo2(a00), lo2(a01)}, {hi2(a00), hi2(a01)},
            {lo2(a10), lo2(a11)}, {hi2(a10), hi2(a11)},
            {lo2(a20), lo2(a21)}, {hi2(a20), hi2(a21)},
            {lo2(a30), lo2(a31)}, {hi2(a30), hi2(a31)}};
        #pragma unroll
        for (int p = 0; p < 8; p++) {
            int row = row0 + r0 + p;
            if (row < n) {
                float2 xv = *(const float2*)&g_x1[(size_t)row * DIM + c];
                resid[(r0 + p) * DIM + c    ] = xv.x + v[p][0];
                resid[(r0 + p) * DIM + c + 1] = xv.y + v[p][1];
            }
        }
    }
    __syncthreads();
    // LN2: 16 warps x 4 rows
    #pragma unroll
    for (int q = 0; q < 4; q++) {
        int rl = wid * 4 + q;
        int row = row0 + rl;
        if (row >= n) continue;
        int d = lane * 4;
        float4 v = *(float4*)(resid + rl * DIM + d);
        float s  = v.x + v.y + v.z + v.w;
        float sq = v.x * v.x + v.y * v.y + v.z * v.z + v.w * v.w;
        #pragma unroll
        for (int m = 16; m; m >>= 1) {
            s  += __shfl_xor_sync(0xffffffffu, s,  m);
            sq += __shfl_xor_sync(0xffffffffu, sq, m);
        }
        float mu = s * (1.f / DIM);
        float var = sq * (1.f / DIM) - mu * mu;
        float rs = rsqrtf(var + 1e-5f);
        float4 gv = *(const float4*)(g2 + d);
        float4 blv = *(const float4*)(bl + d);
        float4 o;
        o.x = (v.x - mu) * rs * gv.x + blv.x;
        o.y = (v.y - mu) * rs * gv.y + blv.y;
        o.z = (v.z - mu) * rs * gv.z + blv.z;
        o.w = (v.w - mu) * rs * gv.w + blv.w;
        *(float4*)&out[(size_t)row * DIM + d] = o;
    }
}

// =====================================================================
extern "C" void kernel_launch(void* const* d_in, const int* in_sizes, int n_in,
                              void* d_out, int out_size) {
    const float* x    = (const float*)d_in[0];
    const void*  ei   = (const void*)d_in[1];   // edge_index [2,E]; row 0 = src; dtype auto-detected
    const float* Winw = (const float*)d_in[2];
    const float* Winb = (const float*)d_in[3];
    const float* Wupw = (const float*)d_in[4];
    const float* Wupb = (const float*)d_in[5];
    const float* Wouw = (const float*)d_in[6];
    const float* Woub = (const float*)d_in[7];
    const float* ln1g = (const float*)d_in[8];
    const float* ln1b = (const float*)d_in[9];
    const float* ln2g = (const float*)d_in[10];
    const float* ln2b = (const float*)d_in[11];
    const float* f1w  = (const float*)d_in[12];
    const float* f1b  = (const float*)d_in[13];
    const float* f2w  = (const float*)d_in[14];
    const float* f2b  = (const float*)d_in[15];
    float* out = (float*)d_out;

    const int n = in_sizes[0] / DIM;

    const int SMEM_WIN  = (DIM * 256 + DIM * 68) * 4;
    const int SMEM_MSG1 = (DIM * 256 + 2 * DIM * 36) * 4 + (32 * KNN + 1) * 4;
    const int SMEM_MSG2 = (DIM * 256 + DIM * 68) * 4;
    const int SMEM_FFN1 = (DIM * 256 + DIM * 68) * 4;
    const int SMEM_FFN2 = (DIM * 256 + DIM * 68) * 4;

    cudaFuncSetAttribute(k_win,  cudaFuncAttributeMaxDynamicSharedMemorySize, SMEM_WIN);
    cudaFuncSetAttribute(k_msg1, cudaFuncAttributeMaxDynamicSharedMemorySize, SMEM_MSG1);
    cudaFuncSetAttribute(k_msg2, cudaFuncAttributeMaxDynamicSharedMemorySize, SMEM_MSG2);
    cudaFuncSetAttribute(k_ffn1, cudaFuncAttributeMaxDynamicSharedMemorySize, SMEM_FFN1);
    cudaFuncSetAttribute(k_ffn2, cudaFuncAttributeMaxDynamicSharedMemorySize, SMEM_FFN2);

    dim3 ga((n + 127) / 128);
    dim3 gm1((n + 31) / 32);
    dim3 gm2((n + 63) / 64);
    dim3 gc((n + 127) / 128, 4);
    dim3 gd((n + 63) / 64);

    k_win <<<ga,  TPB, SMEM_WIN >>>(x, Winw, Winb, n);
    k_msg1<<<gm1, TPB, SMEM_MSG1>>>(ei, Wupw, Wupb, n);
    k_msg2<<<gm2, TPB, SMEM_MSG2>>>(x, Wouw, Woub, ln1g, ln1b, n);
    k_ffn1<<<gc,  TPB, SMEM_FFN1>>>(f1w, f1b, n);
    k_ffn2<<<gd,  TPB, SMEM_FFN2>>>(f2w, f2b, ln2g, ln2b, out, n);
}

// round 6
// speedup vs baseline: 1.5008x; 1.3679x over previous
#include <cuda_runtime.h>
#include <cstdint>
#include <math.h>

#define DIM 128
#define FFN 512
#define KNN 9
#define TPB 256
#define RT  128      // rows per CTA tile
#define KPH 64       // k-depth per phase
#define XDS 256      // Xd row stride in floats (RT rows, duplicated pairs)
#define NMAX 50000

typedef unsigned long long ull;

// ---- packed f32x2 helpers ----
__device__ __forceinline__ ull ffma2(ull a, ull b, ull c) {
    ull d;
    asm("fma.rn.f32x2 %0, %1, %2, %3;" : "=l"(d) : "l"(a), "l"(b), "l"(c));
    return d;
}
__device__ __forceinline__ ull add2(ull a, ull b) {
    ull d;
    asm("add.rn.f32x2 %0, %1, %2;" : "=l"(d) : "l"(a), "l"(b));
    return d;
}
__device__ __forceinline__ ull dup2(float v) {
    unsigned u = __float_as_uint(v);
    ull r;
    asm("mov.b64 %0, {%1, %1};" : "=l"(r) : "r"(u));
    return r;
}
__device__ __forceinline__ float lo2(ull a) {
    unsigned l, h;
    asm("mov.b64 {%0, %1}, %2;" : "=r"(l), "=r"(h) : "l"(a));
    return __uint_as_float(l);
}
__device__ __forceinline__ float hi2(ull a) {
    unsigned l, h;
    asm("mov.b64 {%0, %1}, %2;" : "=r"(l), "=r"(h) : "l"(a));
    return __uint_as_float(h);
}
__device__ __forceinline__ float gelu_exact(float v) {
    return 0.5f * v * (1.0f + erff(v * 0.70710678118654752f));
}

// ---- scratch (static device globals; no allocations anywhere) ----
__device__ float g_h [(size_t)NMAX * DIM];
__device__ float g_h2[(size_t)NMAX * DIM];
__device__ float g_x1[(size_t)NMAX * DIM];
__device__ float g_t [(size_t)NMAX * FFN];

// =====================================================================
// Staging helpers
// =====================================================================
// Weights: Ws[k][.] holds 128 cols with quads interleaved so that the 16
// column-groups read lane-contiguous 256B: dest quad = (q&1)*16 + (q>>1).
__device__ __forceinline__ void stage_w(float* Ws, const float* __restrict__ W,
        int krow0, int ldw, int colbase, int tid) {
    #pragma unroll
    for (int p = 0; p < 8; p++) {
        int i = tid + p * TPB;            // 2048 float4s
        int k = i >> 5, q = i & 31;
        int dq = ((q & 1) << 4) + (q >> 1);
        *(float4*)(Ws + k * 128 + dq * 4) =
            *(const float4*)(W + (size_t)(krow0 + k) * ldw + colbase + q * 4);
    }
}

// x staged duplicated: Xd[k][2r] = (x_r, x_r). Lanes map to rows (conflict-free
// STS.64); the strided gmem reads are absorbed by L1/L2 sector sharing.
__device__ __forceinline__ void stage_x(float* Xd, const float* __restrict__ src,
        int lds, int k0, int row0, int n, int tid) {
    const int rq = tid & 31, kb = tid >> 5;   // kb: 8 k-octets
    #pragma unroll
    for (int pass = 0; pass < 4; pass++) {
        int r = pass * 32 + rq;
        int row = row0 + r;
        float4 v0 = make_float4(0.f, 0.f, 0.f, 0.f), v1 = v0;
        if (row < n) {
            const float* p = src + (size_t)row * lds + k0 + kb * 8;
            v0 = *(const float4*)p;
            v1 = *(const float4*)(p + 4);
        }
        float* xb = Xd + (kb * 8) * XDS + 2 * r;
        *(ull*)(xb          ) = dup2(v0.x);
        *(ull*)(xb + XDS    ) = dup2(v0.y);
        *(ull*)(xb + XDS * 2) = dup2(v0.z);
        *(ull*)(xb + XDS * 3) = dup2(v0.w);
        *(ull*)(xb + XDS * 4) = dup2(v1.x);
        *(ull*)(xb + XDS * 5) = dup2(v1.y);
        *(ull*)(xb + XDS * 6) = dup2(v1.z);
        *(ull*)(xb + XDS * 7) = dup2(v1.w);
    }
}

// =====================================================================
// Core 8x8 register-tile MMA over one 64-deep k-phase.
// a-operand: duplicated x pair (warp-broadcast LDS), b: plain weight pairs.
// =====================================================================
__device__ __forceinline__ void mma_phase(const float* Ws, const float* Xd,
        int cg, int rg, ull acc[8][4]) {
    const float* wpA = Ws + cg * 4;        // interleaved layout: A quads
    const float* wpB = Ws + 64 + cg * 4;   // B quads
    const float* xp  = Xd + rg * 16;
    #pragma unroll 2
    for (int k = 0; k < KPH; k++) {
        ulonglong2 wA = *(const ulonglong2*)(wpA + k * 128);
        ulonglong2 wB = *(const ulonglong2*)(wpB + k * 128);
        const float* xk = xp + k * XDS;
        ulonglong2 x0 = *(const ulonglong2*)(xk);
        ulonglong2 x1 = *(const ulonglong2*)(xk + 4);
        ulonglong2 x2 = *(const ulonglong2*)(xk + 8);
        ulonglong2 x3 = *(const ulonglong2*)(xk + 12);
        #define ROWF(i, xv)                                                     \
            acc[i][0] = ffma2(xv, wA.x, acc[i][0]);                             \
            acc[i][1] = ffma2(xv, wA.y, acc[i][1]);                             \
            acc[i][2] = ffma2(xv, wB.x, acc[i][2]);                             \
            acc[i][3] = ffma2(xv, wB.y, acc[i][3]);
        ROWF(0, x0.x) ROWF(1, x0.y) ROWF(2, x1.x) ROWF(3, x1.y)
        ROWF(4, x2.x) ROWF(5, x2.y) ROWF(6, x3.x) ROWF(7, x3.y)
        #undef ROWF
    }
}

__device__ __forceinline__ void acc_init(ull acc[8][4], const float* __restrict__ bp) {
    ull b0 = *(const ull*)(bp), b1 = *(const ull*)(bp + 2);
    ull b2 = *(const ull*)(bp + 4), b3 = *(const ull*)(bp + 6);
    #pragma unroll
    for (int r = 0; r < 8; r++) {
        acc[r][0] = b0; acc[r][1] = b1; acc[r][2] = b2; acc[r][3] = b3;
    }
}

// residual add (packed) into smem resid buffer
__device__ __forceinline__ void resid_store(float* resid, ull acc[8][4],
        const float* __restrict__ xres, int row0, int n, int cg, int rg) {
    const int c = cg * 8;
    #pragma unroll
    for (int r = 0; r < 8; r++) {
        int rl = rg * 8 + r;
        int row = row0 + rl;
        if (row < n) {
            ulonglong2 x0 = *(const ulonglong2*)(xres + (size_t)row * DIM + c);
            ulonglong2 x1 = *(const ulonglong2*)(xres + (size_t)row * DIM + c + 4);
            ulonglong2 p0, p1;
            p0.x = add2(acc[r][0], x0.x); p0.y = add2(acc[r][1], x0.y);
            p1.x = add2(acc[r][2], x1.x); p1.y = add2(acc[r][3], x1.y);
            *(ulonglong2*)(resid + rl * DIM + c) = p0;
            *(ulonglong2*)(resid + rl * DIM + c + 4) = p1;
        }
    }
}

__device__ __forceinline__ void ln_rows(const float* resid,
        const float* __restrict__ gam, const float* __restrict__ bet,
        float* __restrict__ dst, int dstride, int row0, int n, int tid) {
    const int wid = tid >> 5, lane = tid & 31;
    const int d = lane * 4;
    float4 gv = *(const float4*)(gam + d);
    float4 bv = *(const float4*)(bet + d);
    for (int rl = wid; rl < RT; rl += 8) {
        int row = row0 + rl;
        if (row >= n) continue;
        float4 v = *(const float4*)(resid + rl * DIM + d);
        float s  = v.x + v.y + v.z + v.w;
        float sq = v.x * v.x + v.y * v.y + v.z * v.z + v.w * v.w;
        #pragma unroll
        for (int m = 16; m; m >>= 1) {
            s  += __shfl_xor_sync(0xffffffffu, s,  m);
            sq += __shfl_xor_sync(0xffffffffu, sq, m);
        }
        float mu = s * (1.f / DIM);
        float var = sq * (1.f / DIM) - mu * mu;
        float rs = rsqrtf(var + 1e-5f);
        float4 o;
        o.x = (v.x - mu) * rs * gv.x + bv.x;
        o.y = (v.y - mu) * rs * gv.y + bv.y;
        o.z = (v.z - mu) * rs * gv.z + bv.z;
        o.w = (v.w - mu) * rs * gv.w + bv.w;
        *(float4*)(dst + (size_t)row * dstride + d) = o;
    }
}

// =====================================================================
// Kernel A: h = x @ W_in + b
// =====================================================================
__global__ __launch_bounds__(TPB, 2) void k_win(const float* __restrict__ x,
        const float* __restrict__ W, const float* __restrict__ b, int n) {
    extern __shared__ float sm[];
    float* Ws = sm;
    float* Xd = sm + KPH * 128;
    const int tid = threadIdx.x;
    const int cg = tid & 15, rg = tid >> 4;
    const int row0 = blockIdx.x * RT;
    const int c = cg * 8;
    ull acc[8][4];
    acc_init(acc, b + c);
    #pragma unroll 1
    for (int ph = 0; ph < 2; ph++) {
        __syncthreads();
        stage_w(Ws, W, ph * KPH, DIM, 0, tid);
        stage_x(Xd, x, DIM, ph * KPH, row0, n, tid);
        __syncthreads();
        mma_phase(Ws, Xd, cg, rg, acc);
    }
    #pragma unroll
    for (int r = 0; r < 8; r++) {
        int row = row0 + rg * 8 + r;
        if (row < n) {
            ulonglong2 p0, p1;
            p0.x = acc[r][0]; p0.y = acc[r][1];
            p1.x = acc[r][2]; p1.y = acc[r][3];
            *(ulonglong2*)(g_h + (size_t)row * DIM + c) = p0;
            *(ulonglong2*)(g_h + (size_t)row * DIM + c + 4) = p1;
        }
    }
}

// =====================================================================
// Kernel B1: h2 = [h | maxdiff] @ W_upd + bu   (K=256 in 4 phases;
// the gather for maxdiff is fused into phase-2/3 x-staging, each gathered
// byte read exactly once).  edge_index dtype auto-detected (int64/int32).
// =====================================================================
__global__ __launch_bounds__(TPB, 2) void k_msg1(const void* __restrict__ eidx,
        const float* __restrict__ Wu, const float* __restrict__ bu, int n) {
    extern __shared__ float sm[];
    float* Ws = sm;
    float* Xd = sm + KPH * 128;
    int* srcb = (int*)(Xd + KPH * XDS);      // RT*KNN
    int* flag = srcb + RT * KNN;
    const int tid = threadIdx.x;
    const int cg = tid & 15, rg = tid >> 4;
    const int row0 = blockIdx.x * RT;
    const int c = cg * 8;
    if (tid == 0) {
        const long long* p64 = (const long long*)eidx;
        int ok = 1;
        #pragma unroll
        for (int i = 0; i < 16; i++) {
            long long v = p64[i];
            if (v < 0 || v >= (long long)n) ok = 0;
        }
        *flag = ok;
    }
    __syncthreads();
    const int is64 = *flag;
    for (int i = tid; i < RT * KNN; i += TPB) {
        int r = i / KNN;
        int row = row0 + r;
        int s = 0;
        if (row < n) {
            size_t e = (size_t)row * KNN + (i - r * KNN);
            long long v = is64 ? ((const long long*)eidx)[e]
                               : (long long)((const int*)eidx)[e];
            s = (int)v;
            s = min(max(s, 0), n - 1);
        }
        srcb[i] = s;
    }
    ull acc[8][4];
    acc_init(acc, bu + c);
    // phases 0-1: h half
    #pragma unroll 1
    for (int ph = 0; ph < 2; ph++) {
        __syncthreads();
        stage_w(Ws, Wu, ph * KPH, DIM, 0, tid);
        stage_x(Xd, g_h, DIM, ph * KPH, row0, n, tid);
        __syncthreads();
        mma_phase(Ws, Xd, cg, rg, acc);
    }
    // phases 2-3: maxdiff half (gather fused into staging)
    #pragma unroll 1
    for (int ph = 0; ph < 2; ph++) {
        __syncthreads();
        stage_w(Ws, Wu, DIM + ph * KPH, DIM, 0, tid);
        {
            const int rq = tid & 31, kb = tid >> 5;
            const int d0 = ph * KPH + kb * 8;
            #pragma unroll 1
            for (int pass = 0; pass < 4; pass++) {
                int r = pass * 32 + rq;
                int row = row0 + r;
                float4 m0 = make_float4(-3.4e38f, -3.4e38f, -3.4e38f, -3.4e38f);
                float4 m1 = m0;
                const int* sp = srcb + r * KNN;
                #pragma unroll
                for (int j = 0; j < KNN; j++) {
                    const float* hp = g_h + (size_t)sp[j] * DIM + d0;
                    float4 a = *(const float4*)hp;
                    float4 bq = *(const float4*)(hp + 4);
                    m0.x = fmaxf(m0.x, a.x);  m0.y = fmaxf(m0.y, a.y);
                    m0.z = fmaxf(m0.z, a.z);  m0.w = fmaxf(m0.w, a.w);
                    m1.x = fmaxf(m1.x, bq.x); m1.y = fmaxf(m1.y, bq.y);
                    m1.z = fmaxf(m1.z, bq.z); m1.w = fmaxf(m1.w, bq.w);
                }
                float4 o0 = make_float4(0.f, 0.f, 0.f, 0.f), o1 = o0;
                if (row < n) {
                    const float* op = g_h + (size_t)row * DIM + d0;
                    float4 a = *(const float4*)op;
                    float4 bq = *(const float4*)(op + 4);
                    o0.x = m0.x - a.x;  o0.y = m0.y - a.y;
                    o0.z = m0.z - a.z;  o0.w = m0.w - a.w;
                    o1.x = m1.x - bq.x; o1.y = m1.y - bq.y;
                    o1.z = m1.z - bq.z; o1.w = m1.w - bq.w;
                }
                float* xb = Xd + (kb * 8) * XDS + 2 * r;
                *(ull*)(xb          ) = dup2(o0.x);
                *(ull*)(xb + XDS    ) = dup2(o0.y);
                *(ull*)(xb + XDS * 2) = dup2(o0.z);
                *(ull*)(xb + XDS * 3) = dup2(o0.w);
                *(ull*)(xb + XDS * 4) = dup2(o1.x);
                *(ull*)(xb + XDS * 5) = dup2(o1.y);
                *(ull*)(xb + XDS * 6) = dup2(o1.z);
                *(ull*)(xb + XDS * 7) = dup2(o1.w);
            }
        }
        __syncthreads();
        mma_phase(Ws, Xd, cg, rg, acc);
    }
    #pragma unroll
    for (int r = 0; r < 8; r++) {
        int row = row0 + rg * 8 + r;
        if (row < n) {
            ulonglong2 p0, p1;
            p0.x = acc[r][0]; p0.y = acc[r][1];
            p1.x = acc[r][2]; p1.y = acc[r][3];
            *(ulonglong2*)(g_h2 + (size_t)row * DIM + c) = p0;
            *(ulonglong2*)(g_h2 + (size_t)row * DIM + c + 4) = p1;
        }
    }
}

// =====================================================================
// Kernel B2: h3 = h2 @ W_out + bo; x1 = LN1(x + h3) -> g_x1
// =====================================================================
__global__ __launch_bounds__(TPB, 2) void k_msg2(const float* __restrict__ x,
        const float* __restrict__ Wo, const float* __restrict__ bo,
        const float* __restrict__ g1, const float* __restrict__ b1, int n) {
    extern __shared__ float sm[];
    float* Ws = sm;
    float* Xd = sm + KPH * 128;
    const int tid = threadIdx.x;
    const int cg = tid & 15, rg = tid >> 4;
    const int row0 = blockIdx.x * RT;
    ull acc[8][4];
    acc_init(acc, bo + cg * 8);
    #pragma unroll 1
    for (int ph = 0; ph < 2; ph++) {
        __syncthreads();
        stage_w(Ws, Wo, ph * KPH, DIM, 0, tid);
        stage_x(Xd, g_h2, DIM, ph * KPH, row0, n, tid);
        __syncthreads();
        mma_phase(Ws, Xd, cg, rg, acc);
    }
    __syncthreads();            // done reading Xd; reuse as resid (RT*128 = 64KB)
    resid_store(Xd, acc, x, row0, n, cg, rg);
    __syncthreads();
    ln_rows(Xd, g1, b1, g_x1, DIM, row0, n, tid);
}

// =====================================================================
// Kernel C: t = gelu(x1 @ ffn1 + b)   (grid.y = 4 col-slices of 128)
// =====================================================================
__global__ __launch_bounds__(TPB, 2) void k_ffn1(const float* __restrict__ W,
        const float* __restrict__ b, int n) {
    extern __shared__ float sm[];
    float* Ws = sm;
    float* Xd = sm + KPH * 128;
    const int tid = threadIdx.x;
    const int cg = tid & 15, rg = tid >> 4;
    const int row0 = blockIdx.x * RT;
    const int colbase = blockIdx.y * 128;
    const int c = cg * 8;
    ull acc[8][4];
    acc_init(acc, b + colbase + c);
    #pragma unroll 1
    for (int ph = 0; ph < 2; ph++) {
        __syncthreads();
        stage_w(Ws, W, ph * KPH, FFN, colbase, tid);
        stage_x(Xd, g_x1, DIM, ph * KPH, row0, n, tid);
        __syncthreads();
        mma_phase(Ws, Xd, cg, rg, acc);
    }
    #pragma unroll
    for (int r = 0; r < 8; r++) {
        int row = row0 + rg * 8 + r;
        if (row < n) {
            float4 f0, f1;
            f0.x = gelu_exact(lo2(acc[r][0])); f0.y = gelu_exact(hi2(acc[r][0]));
            f0.z = gelu_exact(lo2(acc[r][1])); f0.w = gelu_exact(hi2(acc[r][1]));
            f1.x = gelu_exact(lo2(acc[r][2])); f1.y = gelu_exact(hi2(acc[r][2]));
            f1.z = gelu_exact(lo2(acc[r][3])); f1.w = gelu_exact(hi2(acc[r][3]));
            *(float4*)(g_t + (size_t)row * FFN + colbase + c) = f0;
            *(float4*)(g_t + (size_t)row * FFN + colbase + c + 4) = f1;
        }
    }
}

// =====================================================================
// Kernel D: f = t @ ffn2 + b2; out = LN2(x1 + f)   (K=512 in 8 phases)
// =====================================================================
__global__ __launch_bounds__(TPB, 2) void k_ffn2(const float* __restrict__ W,
        const float* __restrict__ b2, const float* __restrict__ g2,
        const float* __restrict__ bl, float* __restrict__ out, int n) {
    extern __shared__ float sm[];
    float* Ws = sm;
    float* Xd = sm + KPH * 128;
    const int tid = threadIdx.x;
    const int cg = tid & 15, rg = tid >> 4;
    const int row0 = blockIdx.x * RT;
    ull acc[8][4];
    acc_init(acc, b2 + cg * 8);
    #pragma unroll 1
    for (int ph = 0; ph < 8; ph++) {
        __syncthreads();
        stage_w(Ws, W, ph * KPH, DIM, 0, tid);
        stage_x(Xd, g_t, FFN, ph * KPH, row0, n, tid);
        __syncthreads();
        mma_phase(Ws, Xd, cg, rg, acc);
    }
    __syncthreads();            // reuse Xd as resid
    resid_store(Xd, acc, g_x1, row0, n, cg, rg);
    __syncthreads();
    ln_rows(Xd, g2, bl, out, DIM, row0, n, tid);
}

// =====================================================================
extern "C" void kernel_launch(void* const* d_in, const int* in_sizes, int n_in,
                              void* d_out, int out_size) {
    const float* x    = (const float*)d_in[0];
    const void*  ei   = (const void*)d_in[1];   // edge_index [2,E]; row 0 = src
    const float* Winw = (const float*)d_in[2];
    const float* Winb = (const float*)d_in[3];
    const float* Wupw = (const float*)d_in[4];
    const float* Wupb = (const float*)d_in[5];
    const float* Wouw = (const float*)d_in[6];
    const float* Woub = (const float*)d_in[7];
    const float* ln1g = (const float*)d_in[8];
    const float* ln1b = (const float*)d_in[9];
    const float* ln2g = (const float*)d_in[10];
    const float* ln2b = (const float*)d_in[11];
    const float* f1w  = (const float*)d_in[12];
    const float* f1b  = (const float*)d_in[13];
    const float* f2w  = (const float*)d_in[14];
    const float* f2b  = (const float*)d_in[15];
    float* out = (float*)d_out;

    const int n = in_sizes[0] / DIM;

    const int SMEM_GEMM = (KPH * 128 + KPH * XDS) * 4;                 // 96 KB
    const int SMEM_MSG1 = SMEM_GEMM + (RT * KNN + 1) * 4;              // +4.6 KB

    cudaFuncSetAttribute(k_win,  cudaFuncAttributeMaxDynamicSharedMemorySize, SMEM_GEMM);
    cudaFuncSetAttribute(k_msg1, cudaFuncAttributeMaxDynamicSharedMemorySize, SMEM_MSG1);
    cudaFuncSetAttribute(k_msg2, cudaFuncAttributeMaxDynamicSharedMemorySize, SMEM_GEMM);
    cudaFuncSetAttribute(k_ffn1, cudaFuncAttributeMaxDynamicSharedMemorySize, SMEM_GEMM);
    cudaFuncSetAttribute(k_ffn2, cudaFuncAttributeMaxDynamicSharedMemorySize, SMEM_GEMM);

    const int nb = (n + RT - 1) / RT;
    dim3 gc(nb, 4);

    k_win <<<nb, TPB, SMEM_GEMM>>>(x, Winw, Winb, n);
    k_msg1<<<nb, TPB, SMEM_MSG1>>>(ei, Wupw, Wupb, n);
    k_msg2<<<nb, TPB, SMEM_GEMM>>>(x, Wouw, Woub, ln1g, ln1b, n);
    k_ffn1<<<gc, TPB, SMEM_GEMM>>>(f1w, f1b, n);
    k_ffn2<<<nb, TPB, SMEM_GEMM>>>(f2w, f2b, ln2g, ln2b, out, n);
}

// round 7
// speedup vs baseline: 1.5522x; 1.0343x over previous
#include <cuda_runtime.h>
#include <cstdint>
#include <math.h>

#define DIM 128
#define FFN 512
#define KNN 9
#define TPB 256
#define RT  64       // rows per CTA tile
#define KPH 64       // k-depth per phase
#define XDS 128      // Xd row stride in floats (RT rows, duplicated pairs)
#define NMAX 50000

typedef unsigned long long ull;

// ---- packed f32x2 helpers ----
__device__ __forceinline__ ull ffma2(ull a, ull b, ull c) {
    ull d;
    asm("fma.rn.f32x2 %0, %1, %2, %3;" : "=l"(d) : "l"(a), "l"(b), "l"(c));
    return d;
}
__device__ __forceinline__ ull add2(ull a, ull b) {
    ull d;
    asm("add.rn.f32x2 %0, %1, %2;" : "=l"(d) : "l"(a), "l"(b));
    return d;
}
__device__ __forceinline__ ull dup2(float v) {
    unsigned u = __float_as_uint(v);
    ull r;
    asm("mov.b64 %0, {%1, %1};" : "=l"(r) : "r"(u));
    return r;
}
__device__ __forceinline__ float lo2(ull a) {
    unsigned l, h;
    asm("mov.b64 {%0, %1}, %2;" : "=r"(l), "=r"(h) : "l"(a));
    return __uint_as_float(l);
}
__device__ __forceinline__ float hi2(ull a) {
    unsigned l, h;
    asm("mov.b64 {%0, %1}, %2;" : "=r"(l), "=r"(h) : "l"(a));
    return __uint_as_float(h);
}
__device__ __forceinline__ float gelu_exact(float v) {
    return 0.5f * v * (1.0f + erff(v * 0.70710678118654752f));
}

// ---- scratch (static device globals; no allocations anywhere) ----
__device__ float g_h [(size_t)NMAX * DIM];
__device__ float g_h2[(size_t)NMAX * DIM];
__device__ float g_x1[(size_t)NMAX * DIM];
__device__ float g_t [(size_t)NMAX * FFN];

// =====================================================================
// Staging helpers
// =====================================================================
// Weights: Ws[k][.] holds 128 cols, quads interleaved so the 16 column
// groups read lane-contiguous 256B: dest quad = (q&1)*16 + (q>>1).
__device__ __forceinline__ void stage_w(float* Ws, const float* __restrict__ W,
        int krow0, int ldw, int colbase, int tid) {
    #pragma unroll
    for (int p = 0; p < 8; p++) {
        int i = tid + p * TPB;            // 2048 float4s
        int k = i >> 5, q = i & 31;
        int dq = ((q & 1) << 4) + (q >> 1);
        *(float4*)(Ws + k * 128 + dq * 4) =
            *(const float4*)(W + (size_t)(krow0 + k) * ldw + colbase + q * 4);
    }
}

// x staged duplicated: Xd[k][2r] = (x_r, x_r).
__device__ __forceinline__ void stage_x(float* Xd, const float* __restrict__ src,
        int lds, int k0, int row0, int n, int tid) {
    const int rq = tid & 31, kb = tid >> 5;   // kb: 8 k-octets
    #pragma unroll
    for (int pass = 0; pass < 2; pass++) {
        int r = pass * 32 + rq;
        int row = row0 + r;
        float4 v0 = make_float4(0.f, 0.f, 0.f, 0.f), v1 = v0;
        if (row < n) {
            const float* p = src + (size_t)row * lds + k0 + kb * 8;
            v0 = *(const float4*)p;
            v1 = *(const float4*)(p + 4);
        }
        float* xb = Xd + (kb * 8) * XDS + 2 * r;
        *(ull*)(xb          ) = dup2(v0.x);
        *(ull*)(xb + XDS    ) = dup2(v0.y);
        *(ull*)(xb + XDS * 2) = dup2(v0.z);
        *(ull*)(xb + XDS * 3) = dup2(v0.w);
        *(ull*)(xb + XDS * 4) = dup2(v1.x);
        *(ull*)(xb + XDS * 5) = dup2(v1.y);
        *(ull*)(xb + XDS * 6) = dup2(v1.z);
        *(ull*)(xb + XDS * 7) = dup2(v1.w);
    }
}

// =====================================================================
// Core 4x8 register-tile MMA over one 64-deep k-phase.
// a-operand: duplicated x pair (warp-broadcast LDS), b: plain weight pairs.
// =====================================================================
__device__ __forceinline__ void mma_phase(const float* Ws, const float* Xd,
        int cg, int rg, ull acc[4][4]) {
    const float* wpA = Ws + cg * 4;        // interleaved layout: A quads
    const float* wpB = Ws + 64 + cg * 4;   // B quads
    const float* xp  = Xd + rg * 8;
    #pragma unroll 4
    for (int k = 0; k < KPH; k++) {
        ulonglong2 wA = *(const ulonglong2*)(wpA + k * 128);
        ulonglong2 wB = *(const ulonglong2*)(wpB + k * 128);
        const float* xk = xp + k * XDS;
        ulonglong2 x0 = *(const ulonglong2*)(xk);
        ulonglong2 x1 = *(const ulonglong2*)(xk + 4);
        #define ROWF(i, xv)                                                     \
            acc[i][0] = ffma2(xv, wA.x, acc[i][0]);                             \
            acc[i][1] = ffma2(xv, wA.y, acc[i][1]);                             \
            acc[i][2] = ffma2(xv, wB.x, acc[i][2]);                             \
            acc[i][3] = ffma2(xv, wB.y, acc[i][3]);
        ROWF(0, x0.x) ROWF(1, x0.y) ROWF(2, x1.x) ROWF(3, x1.y)
        #undef ROWF
    }
}

__device__ __forceinline__ void acc_init(ull acc[4][4], const float* __restrict__ bp) {
    ull b0 = *(const ull*)(bp), b1 = *(const ull*)(bp + 2);
    ull b2 = *(const ull*)(bp + 4), b3 = *(const ull*)(bp + 6);
    #pragma unroll
    for (int r = 0; r < 4; r++) {
        acc[r][0] = b0; acc[r][1] = b1; acc[r][2] = b2; acc[r][3] = b3;
    }
}

// residual add (packed) into smem resid buffer
__device__ __forceinline__ void resid_store(float* resid, ull acc[4][4],
        const float* __restrict__ xres, int row0, int n, int cg, int rg) {
    const int c = cg * 8;
    #pragma unroll
    for (int r = 0; r < 4; r++) {
        int rl = rg * 4 + r;
        int row = row0 + rl;
        if (row < n) {
            ulonglong2 x0 = *(const ulonglong2*)(xres + (size_t)row * DIM + c);
            ulonglong2 x1 = *(const ulonglong2*)(xres + (size_t)row * DIM + c + 4);
            ulonglong2 p0, p1;
            p0.x = add2(acc[r][0], x0.x); p0.y = add2(acc[r][1], x0.y);
            p1.x = add2(acc[r][2], x1.x); p1.y = add2(acc[r][3], x1.y);
            *(ulonglong2*)(resid + rl * DIM + c) = p0;
            *(ulonglong2*)(resid + rl * DIM + c + 4) = p1;
        }
    }
}

__device__ __forceinline__ void ln_rows(const float* resid,
        const float* __restrict__ gam, const float* __restrict__ bet,
        float* __restrict__ dst, int dstride, int row0, int n, int tid) {
    const int wid = tid >> 5, lane = tid & 31;
    const int d = lane * 4;
    float4 gv = *(const float4*)(gam + d);
    float4 bv = *(const float4*)(bet + d);
    for (int rl = wid; rl < RT; rl += 8) {
        int row = row0 + rl;
        if (row >= n) continue;
        float4 v = *(const float4*)(resid + rl * DIM + d);
        float s  = v.x + v.y + v.z + v.w;
        float sq = v.x * v.x + v.y * v.y + v.z * v.z + v.w * v.w;
        #pragma unroll
        for (int m = 16; m; m >>= 1) {
            s  += __shfl_xor_sync(0xffffffffu, s,  m);
            sq += __shfl_xor_sync(0xffffffffu, sq, m);
        }
        float mu = s * (1.f / DIM);
        float var = sq * (1.f / DIM) - mu * mu;
        float rs = rsqrtf(var + 1e-5f);
        float4 o;
        o.x = (v.x - mu) * rs * gv.x + bv.x;
        o.y = (v.y - mu) * rs * gv.y + bv.y;
        o.z = (v.z - mu) * rs * gv.z + bv.z;
        o.w = (v.w - mu) * rs * gv.w + bv.w;
        *(float4*)(dst + (size_t)row * dstride + d) = o;
    }
}

// =====================================================================
// Kernel A: h = x @ W_in + b
// =====================================================================
__global__ __launch_bounds__(TPB, 3) void k_win(const float* __restrict__ x,
        const float* __restrict__ W, const float* __restrict__ b, int n) {
    extern __shared__ float sm[];
    float* Ws = sm;
    float* Xd = sm + KPH * 128;
    const int tid = threadIdx.x;
    const int cg = tid & 15, rg = tid >> 4;
    const int row0 = blockIdx.x * RT;
    const int c = cg * 8;
    ull acc[4][4];
    acc_init(acc, b + c);
    #pragma unroll 1
    for (int ph = 0; ph < 2; ph++) {
        __syncthreads();
        stage_w(Ws, W, ph * KPH, DIM, 0, tid);
        stage_x(Xd, x, DIM, ph * KPH, row0, n, tid);
        __syncthreads();
        mma_phase(Ws, Xd, cg, rg, acc);
    }
    #pragma unroll
    for (int r = 0; r < 4; r++) {
        int row = row0 + rg * 4 + r;
        if (row < n) {
            ulonglong2 p0, p1;
            p0.x = acc[r][0]; p0.y = acc[r][1];
            p1.x = acc[r][2]; p1.y = acc[r][3];
            *(ulonglong2*)(g_h + (size_t)row * DIM + c) = p0;
            *(ulonglong2*)(g_h + (size_t)row * DIM + c + 4) = p1;
        }
    }
}

// =====================================================================
// Kernel B1: h2 = [h | maxdiff] @ W_upd + bu  (K=256 in 4 phases; gather
// fused into phase-2/3 staging). edge_index dtype auto-detected.
// =====================================================================
__global__ __launch_bounds__(TPB, 3) void k_msg1(const void* __restrict__ eidx,
        const float* __restrict__ Wu, const float* __restrict__ bu, int n) {
    extern __shared__ float sm[];
    float* Ws = sm;
    float* Xd = sm + KPH * 128;
    int* srcb = (int*)(Xd + KPH * XDS);      // RT*KNN
    int* flag = srcb + RT * KNN;
    const int tid = threadIdx.x;
    const int cg = tid & 15, rg = tid >> 4;
    const int row0 = blockIdx.x * RT;
    const int c = cg * 8;
    if (tid == 0) {
        const long long* p64 = (const long long*)eidx;
        int ok = 1;
        #pragma unroll
        for (int i = 0; i < 16; i++) {
            long long v = p64[i];
            if (v < 0 || v >= (long long)n) ok = 0;
        }
        *flag = ok;
    }
    __syncthreads();
    const int is64 = *flag;
    for (int i = tid; i < RT * KNN; i += TPB) {
        int r = i / KNN;
        int row = row0 + r;
        int s = 0;
        if (row < n) {
            size_t e = (size_t)row * KNN + (i - r * KNN);
            long long v = is64 ? ((const long long*)eidx)[e]
                               : (long long)((const int*)eidx)[e];
            s = (int)v;
            s = min(max(s, 0), n - 1);
        }
        srcb[i] = s;
    }
    ull acc[4][4];
    acc_init(acc, bu + c);
    // phases 0-1: h half
    #pragma unroll 1
    for (int ph = 0; ph < 2; ph++) {
        __syncthreads();
        stage_w(Ws, Wu, ph * KPH, DIM, 0, tid);
        stage_x(Xd, g_h, DIM, ph * KPH, row0, n, tid);
        __syncthreads();
        mma_phase(Ws, Xd, cg, rg, acc);
    }
    // phases 2-3: maxdiff half (gather fused into staging)
    #pragma unroll 1
    for (int ph = 0; ph < 2; ph++) {
        __syncthreads();
        stage_w(Ws, Wu, DIM + ph * KPH, DIM, 0, tid);
        {
            const int rq = tid & 31, kb = tid >> 5;
            const int d0 = ph * KPH + kb * 8;
            #pragma unroll 1
            for (int pass = 0; pass < 2; pass++) {
                int r = pass * 32 + rq;
                int row = row0 + r;
                float4 m0 = make_float4(-3.4e38f, -3.4e38f, -3.4e38f, -3.4e38f);
                float4 m1 = m0;
                const int* sp = srcb + r * KNN;
                #pragma unroll
                for (int j = 0; j < KNN; j++) {
                    const float* hp = g_h + (size_t)sp[j] * DIM + d0;
                    float4 a = *(const float4*)hp;
                    float4 bq = *(const float4*)(hp + 4);
                    m0.x = fmaxf(m0.x, a.x);  m0.y = fmaxf(m0.y, a.y);
                    m0.z = fmaxf(m0.z, a.z);  m0.w = fmaxf(m0.w, a.w);
                    m1.x = fmaxf(m1.x, bq.x); m1.y = fmaxf(m1.y, bq.y);
                    m1.z = fmaxf(m1.z, bq.z); m1.w = fmaxf(m1.w, bq.w);
                }
                float4 o0 = make_float4(0.f, 0.f, 0.f, 0.f), o1 = o0;
                if (row < n) {
                    const float* op = g_h + (size_t)row * DIM + d0;
                    float4 a = *(const float4*)op;
                    float4 bq = *(const float4*)(op + 4);
                    o0.x = m0.x - a.x;  o0.y = m0.y - a.y;
                    o0.z = m0.z - a.z;  o0.w = m0.w - a.w;
                    o1.x = m1.x - bq.x; o1.y = m1.y - bq.y;
                    o1.z = m1.z - bq.z; o1.w = m1.w - bq.w;
                }
                float* xb = Xd + (kb * 8) * XDS + 2 * r;
                *(ull*)(xb          ) = dup2(o0.x);
                *(ull*)(xb + XDS    ) = dup2(o0.y);
                *(ull*)(xb + XDS * 2) = dup2(o0.z);
                *(ull*)(xb + XDS * 3) = dup2(o0.w);
                *(ull*)(xb + XDS * 4) = dup2(o1.x);
                *(ull*)(xb + XDS * 5) = dup2(o1.y);
                *(ull*)(xb + XDS * 6) = dup2(o1.z);
                *(ull*)(xb + XDS * 7) = dup2(o1.w);
            }
        }
        __syncthreads();
        mma_phase(Ws, Xd, cg, rg, acc);
    }
    #pragma unroll
    for (int r = 0; r < 4; r++) {
        int row = row0 + rg * 4 + r;
        if (row < n) {
            ulonglong2 p0, p1;
            p0.x = acc[r][0]; p0.y = acc[r][1];
            p1.x = acc[r][2]; p1.y = acc[r][3];
            *(ulonglong2*)(g_h2 + (size_t)row * DIM + c) = p0;
            *(ulonglong2*)(g_h2 + (size_t)row * DIM + c + 4) = p1;
        }
    }
}

// =====================================================================
// Kernel B2: h3 = h2 @ W_out + bo; x1 = LN1(x + h3) -> g_x1
// =====================================================================
__global__ __launch_bounds__(TPB, 3) void k_msg2(const float* __restrict__ x,
        const float* __restrict__ Wo, const float* __restrict__ bo,
        const float* __restrict__ g1, const float* __restrict__ b1, int n) {
    extern __shared__ float sm[];
    float* Ws = sm;
    float* Xd = sm + KPH * 128;
    const int tid = threadIdx.x;
    const int cg = tid & 15, rg = tid >> 4;
    const int row0 = blockIdx.x * RT;
    ull acc[4][4];
    acc_init(acc, bo + cg * 8);
    #pragma unroll 1
    for (int ph = 0; ph < 2; ph++) {
        __syncthreads();
        stage_w(Ws, Wo, ph * KPH, DIM, 0, tid);
        stage_x(Xd, g_h2, DIM, ph * KPH, row0, n, tid);
        __syncthreads();
        mma_phase(Ws, Xd, cg, rg, acc);
    }
    __syncthreads();            // done with Ws/Xd; reuse whole smem as resid
    float* resid = sm;          // RT*DIM = 32KB
    resid_store(resid, acc, x, row0, n, cg, rg);
    __syncthreads();
    ln_rows(resid, g1, b1, g_x1, DIM, row0, n, tid);
}

// =====================================================================
// Kernel C: t = gelu(x1 @ ffn1 + b)   (grid.y = 4 col-slices of 128)
// =====================================================================
__global__ __launch_bounds__(TPB, 3) void k_ffn1(const float* __restrict__ W,
        const float* __restrict__ b, int n) {
    extern __shared__ float sm[];
    float* Ws = sm;
    float* Xd = sm + KPH * 128;
    const int tid = threadIdx.x;
    const int cg = tid & 15, rg = tid >> 4;
    const int row0 = blockIdx.x * RT;
    const int colbase = blockIdx.y * 128;
    const int c = cg * 8;
    ull acc[4][4];
    acc_init(acc, b + colbase + c);
    #pragma unroll 1
    for (int ph = 0; ph < 2; ph++) {
        __syncthreads();
        stage_w(Ws, W, ph * KPH, FFN, colbase, tid);
        stage_x(Xd, g_x1, DIM, ph * KPH, row0, n, tid);
        __syncthreads();
        mma_phase(Ws, Xd, cg, rg, acc);
    }
    #pragma unroll
    for (int r = 0; r < 4; r++) {
        int row = row0 + rg * 4 + r;
        if (row < n) {
            float4 f0, f1;
            f0.x = gelu_exact(lo2(acc[r][0])); f0.y = gelu_exact(hi2(acc[r][0]));
            f0.z = gelu_exact(lo2(acc[r][1])); f0.w = gelu_exact(hi2(acc[r][1]));
            f1.x = gelu_exact(lo2(acc[r][2])); f1.y = gelu_exact(hi2(acc[r][2]));
            f1.z = gelu_exact(lo2(acc[r][3])); f1.w = gelu_exact(hi2(acc[r][3]));
            *(float4*)(g_t + (size_t)row * FFN + colbase + c) = f0;
            *(float4*)(g_t + (size_t)row * FFN + colbase + c + 4) = f1;
        }
    }
}

// =====================================================================
// Kernel D: f = t @ ffn2 + b2; out = LN2(x1 + f)   (K=512 in 8 phases)
// =====================================================================
__global__ __launch_bounds__(TPB, 3) void k_ffn2(const float* __restrict__ W,
        const float* __restrict__ b2, const float* __restrict__ g2,
        const float* __restrict__ bl, float* __restrict__ out, int n) {
    extern __shared__ float sm[];
    float* Ws = sm;
    float* Xd = sm + KPH * 128;
    const int tid = threadIdx.x;
    const int cg = tid & 15, rg = tid >> 4;
    const int row0 = blockIdx.x * RT;
    ull acc[4][4];
    acc_init(acc, b2 + cg * 8);
    #pragma unroll 1
    for (int ph = 0; ph < 8; ph++) {
        __syncthreads();
        stage_w(Ws, W, ph * KPH, DIM, 0, tid);
        stage_x(Xd, g_t, FFN, ph * KPH, row0, n, tid);
        __syncthreads();
        mma_phase(Ws, Xd, cg, rg, acc);
    }
    __syncthreads();            // reuse whole smem as resid
    float* resid = sm;
    resid_store(resid, acc, g_x1, row0, n, cg, rg);
    __syncthreads();
    ln_rows(resid, g2, bl, out, DIM, row0, n, tid);
}

// =====================================================================
extern "C" void kernel_launch(void* const* d_in, const int* in_sizes, int n_in,
                              void* d_out, int out_size) {
    const float* x    = (const float*)d_in[0];
    const void*  ei   = (const void*)d_in[1];   // edge_index [2,E]; row 0 = src
    const float* Winw = (const float*)d_in[2];
    const float* Winb = (const float*)d_in[3];
    const float* Wupw = (const float*)d_in[4];
    const float* Wupb = (const float*)d_in[5];
    const float* Wouw = (const float*)d_in[6];
    const float* Woub = (const float*)d_in[7];
    const float* ln1g = (const float*)d_in[8];
    const float* ln1b = (const float*)d_in[9];
    const float* ln2g = (const float*)d_in[10];
    const float* ln2b = (const float*)d_in[11];
    const float* f1w  = (const float*)d_in[12];
    const float* f1b  = (const float*)d_in[13];
    const float* f2w  = (const float*)d_in[14];
    const float* f2b  = (const float*)d_in[15];
    float* out = (float*)d_out;

    const int n = in_sizes[0] / DIM;

    const int SMEM_GEMM = (KPH * 128 + KPH * XDS) * 4;                 // 64 KB
    const int SMEM_MSG1 = SMEM_GEMM + (RT * KNN + 1) * 4;              // +2.3 KB

    cudaFuncSetAttribute(k_win,  cudaFuncAttributeMaxDynamicSharedMemorySize, SMEM_GEMM);
    cudaFuncSetAttribute(k_msg1, cudaFuncAttributeMaxDynamicSharedMemorySize, SMEM_MSG1);
    cudaFuncSetAttribute(k_msg2, cudaFuncAttributeMaxDynamicSharedMemorySize, SMEM_GEMM);
    cudaFuncSetAttribute(k_ffn1, cudaFuncAttributeMaxDynamicSharedMemorySize, SMEM_GEMM);
    cudaFuncSetAttribute(k_ffn2, cudaFuncAttributeMaxDynamicSharedMemorySize, SMEM_GEMM);

    const int nb = (n + RT - 1) / RT;
    dim3 gc(nb, 4);

    k_win <<<nb, TPB, SMEM_GEMM>>>(x, Winw, Winb, n);
    k_msg1<<<nb, TPB, SMEM_MSG1>>>(ei, Wupw, Wupb, n);
    k_msg2<<<nb, TPB, SMEM_GEMM>>>(x, Wouw, Woub, ln1g, ln1b, n);
    k_ffn1<<<gc, TPB, SMEM_GEMM>>>(f1w, f1b, n);
    k_ffn2<<<nb, TPB, SMEM_GEMM>>>(f2w, f2b, ln2g, ln2b, out, n);
}

// round 9
// speedup vs baseline: 1.9763x; 1.2732x over previous
#include <cuda_runtime.h>
#include <cstdint>
#include <math.h>

#define DIM 128
#define FFN 512
#define KNN 9
#define TPB 256
#define RT  128      // rows per CTA tile
#define KPH 64       // k-depth per phase
#define NMAX 50000

// Xd blocked-linear layout: float offset = (k>>2)*XB + (k&3)*XJ + 4*pair
// pair p holds dup(row 2p) | dup(row 2p+1) in 16B. XB=1044 (==20 mod 32 banks
// -> spreads concurrent k-quads), XJ=260. All strides 16B-aligned.
#define XB 1044
#define XJ 260
#define XD_FLOATS (16 * XB)   // 16704 floats

typedef unsigned long long ull;

// ---- packed f32x2 helpers ----
__device__ __forceinline__ ull ffma2(ull a, ull b, ull c) {
    ull d;
    asm("fma.rn.f32x2 %0, %1, %2, %3;" : "=l"(d) : "l"(a), "l"(b), "l"(c));
    return d;
}
__device__ __forceinline__ ull add2(ull a, ull b) {
    ull d;
    asm("add.rn.f32x2 %0, %1, %2;" : "=l"(d) : "l"(a), "l"(b));
    return d;
}
__device__ __forceinline__ ull dup2(float v) {
    unsigned u = __float_as_uint(v);
    ull r;
    asm("mov.b64 %0, {%1, %1};" : "=l"(r) : "r"(u));
    return r;
}
__device__ __forceinline__ float lo2(ull a) {
    unsigned l, h;
    asm("mov.b64 {%0, %1}, %2;" : "=r"(l), "=r"(h) : "l"(a));
    return __uint_as_float(l);
}
__device__ __forceinline__ float hi2(ull a) {
    unsigned l, h;
    asm("mov.b64 {%0, %1}, %2;" : "=r"(l), "=r"(h) : "l"(a));
    return __uint_as_float(h);
}
__device__ __forceinline__ float gelu_exact(float v) {
    return 0.5f * v * (1.0f + erff(v * 0.70710678118654752f));
}

// ---- scratch (static device globals; no allocations anywhere) ----
__device__ float g_h [(size_t)NMAX * DIM];
__device__ float g_h2[(size_t)NMAX * DIM];
__device__ float g_x1[(size_t)NMAX * DIM];
__device__ float g_t [(size_t)NMAX * FFN];

// =====================================================================
// Staging
// =====================================================================
// Weights: Ws[k][.] 128 cols, quads interleaved: dest quad = (q&1)*16 + (q>>1)
__device__ __forceinline__ void stage_w(float* Ws, const float* __restrict__ W,
        int krow0, int ldw, int colbase, int tid) {
    #pragma unroll
    for (int p = 0; p < 8; p++) {
        int i = tid + p * TPB;            // 2048 float4s
        int k = i >> 5, q = i & 31;
        int dq = ((q & 1) << 4) + (q >> 1);
        *(float4*)(Ws + k * 128 + dq * 4) =
            *(const float4*)(W + (size_t)(krow0 + k) * ldw + colbase + q * 4);
    }
}

// Coalesced transpose-dup x staging. Thread = (k-quad m, rowpair parity rp).
// LDG.128 reads contiguous 16B row chunks (warp: 4 rows x 256B = ~8 lines).
__device__ __forceinline__ void stage_x(float* Xd, const float* __restrict__ src,
        int lds, int k0, int row0, int n, int tid) {
    const int m  = tid & 15;
    const int rp = (tid >> 4) & 1;
    const int w  = tid >> 5;
    #pragma unroll
    for (int it = 0; it < 4; it++) {
        int p = (((w << 2) + it) << 1) + rp;    // pair 0..63
        int rowA = row0 + 2 * p, rowB = rowA + 1;
        float4 a = make_float4(0.f, 0.f, 0.f, 0.f), b = a;
        if (rowA < n) a = *(const float4*)(src + (size_t)rowA * lds + k0 + 4 * m);
        if (rowB < n) b = *(const float4*)(src + (size_t)rowB * lds + k0 + 4 * m);
        float* xb = Xd + m * XB + 4 * p;
        ulonglong2 t;
        t.x = dup2(a.x); t.y = dup2(b.x); *(ulonglong2*)(xb         ) = t;
        t.x = dup2(a.y); t.y = dup2(b.y); *(ulonglong2*)(xb + XJ    ) = t;
        t.x = dup2(a.z); t.y = dup2(b.z); *(ulonglong2*)(xb + 2 * XJ) = t;
        t.x = dup2(a.w); t.y = dup2(b.w); *(ulonglong2*)(xb + 3 * XJ) = t;
    }
}

// =====================================================================
// 8x8 register-tile MMA over one 64-deep k-phase (blocked-linear Xd).
// Per k: 2 weight LDS.128 + 4 x LDS.128 (broadcast) + 32 FFMA2.
// =====================================================================
__device__ __forceinline__ void mma_phase(const float* Ws, const float* Xd,
        int cg, int rg, ull acc[8][4]) {
    const float* wp = Ws + cg * 4;
    const float* xp = Xd + rg * 16;
    #pragma unroll 1
    for (int m = 0; m < 16; m++) {
        const float* wk = wp + m * 512;
        const float* xk = xp + m * XB;
        #pragma unroll
        for (int j = 0; j < 4; j++) {
            ulonglong2 wA = *(const ulonglong2*)(wk + j * 128);
            ulonglong2 wB = *(const ulonglong2*)(wk + j * 128 + 64);
            const float* xj = xk + j * XJ;
            ulonglong2 x0 = *(const ulonglong2*)(xj);
            ulonglong2 x1 = *(const ulonglong2*)(xj + 4);
            ulonglong2 x2 = *(const ulonglong2*)(xj + 8);
            ulonglong2 x3 = *(const ulonglong2*)(xj + 12);
            #define ROWF(i, xv)                                                 \
                acc[i][0] = ffma2(xv, wA.x, acc[i][0]);                         \
                acc[i][1] = ffma2(xv, wA.y, acc[i][1]);                         \
                acc[i][2] = ffma2(xv, wB.x, acc[i][2]);                         \
                acc[i][3] = ffma2(xv, wB.y, acc[i][3]);
            ROWF(0, x0.x) ROWF(1, x0.y) ROWF(2, x1.x) ROWF(3, x1.y)
            ROWF(4, x2.x) ROWF(5, x2.y) ROWF(6, x3.x) ROWF(7, x3.y)
            #undef ROWF
        }
    }
}

__device__ __forceinline__ void acc_init(ull acc[8][4], const float* __restrict__ bp) {
    ull b0 = *(const ull*)(bp), b1 = *(const ull*)(bp + 2);
    ull b2 = *(const ull*)(bp + 4), b3 = *(const ull*)(bp + 6);
    #pragma unroll
    for (int r = 0; r < 8; r++) {
        acc[r][0] = b0; acc[r][1] = b1; acc[r][2] = b2; acc[r][3] = b3;
    }
}

// acc[r] holds one row's 8 columns as 4 packed (lo,hi)=adjacent-column pairs,
// so direct packed stores are correct.
__device__ __forceinline__ void store_rows(float* __restrict__ dst, int dstride,
        ull acc[8][4], int row0, int n, int cg, int rg) {
    const int c = cg * 8;
    #pragma unroll
    for (int r = 0; r < 8; r++) {
        int row = row0 + rg * 8 + r;
        if (row < n) {
            ulonglong2 p0, p1;
            p0.x = acc[r][0]; p0.y = acc[r][1];
            p1.x = acc[r][2]; p1.y = acc[r][3];
            *(ulonglong2*)(dst + (size_t)row * dstride + c) = p0;
            *(ulonglong2*)(dst + (size_t)row * dstride + c + 4) = p1;
        }
    }
}

// residual add (packed) into smem resid buffer
__device__ __forceinline__ void resid_store(float* resid, ull acc[8][4],
        const float* __restrict__ xres, int row0, int n, int cg, int rg) {
    const int c = cg * 8;
    #pragma unroll
    for (int r = 0; r < 8; r++) {
        int rl = rg * 8 + r;
        int row = row0 + rl;
        if (row < n) {
            ulonglong2 x0 = *(const ulonglong2*)(xres + (size_t)row * DIM + c);
            ulonglong2 x1 = *(const ulonglong2*)(xres + (size_t)row * DIM + c + 4);
            ulonglong2 p0, p1;
            p0.x = add2(acc[r][0], x0.x); p0.y = add2(acc[r][1], x0.y);
            p1.x = add2(acc[r][2], x1.x); p1.y = add2(acc[r][3], x1.y);
            *(ulonglong2*)(resid + rl * DIM + c) = p0;
            *(ulonglong2*)(resid + rl * DIM + c + 4) = p1;
        }
    }
}

__device__ __forceinline__ void ln_rows(const float* resid,
        const float* __restrict__ gam, const float* __restrict__ bet,
        float* __restrict__ dst, int dstride, int row0, int n, int tid) {
    const int wid = tid >> 5, lane = tid & 31;
    const int d = lane * 4;
    float4 gv = *(const float4*)(gam + d);
    float4 bv = *(const float4*)(bet + d);
    for (int rl = wid; rl < RT; rl += 8) {
        int row = row0 + rl;
        if (row >= n) continue;
        float4 v = *(const float4*)(resid + rl * DIM + d);
        float s  = v.x + v.y + v.z + v.w;
        float sq = v.x * v.x + v.y * v.y + v.z * v.z + v.w * v.w;
        #pragma unroll
        for (int m = 16; m; m >>= 1) {
            s  += __shfl_xor_sync(0xffffffffu, s,  m);
            sq += __shfl_xor_sync(0xffffffffu, sq, m);
        }
        float mu = s * (1.f / DIM);
        float var = sq * (1.f / DIM) - mu * mu;
        float rs = rsqrtf(var + 1e-5f);
        float4 o;
        o.x = (v.x - mu) * rs * gv.x + bv.x;
        o.y = (v.y - mu) * rs * gv.y + bv.y;
        o.z = (v.z - mu) * rs * gv.z + bv.z;
        o.w = (v.w - mu) * rs * gv.w + bv.w;
        *(float4*)(dst + (size_t)row * dstride + d) = o;
    }
}

// =====================================================================
// Kernel A: h = x @ W_in + b
// =====================================================================
__global__ __launch_bounds__(TPB, 2) void k_win(const float* __restrict__ x,
        const float* __restrict__ W, const float* __restrict__ b, int n) {
    extern __shared__ float sm[];
    float* Ws = sm;
    float* Xd = sm + KPH * 128;
    const int tid = threadIdx.x;
    const int cg = tid & 15, rg = tid >> 4;
    const int row0 = blockIdx.x * RT;
    ull acc[8][4];
    acc_init(acc, b + cg * 8);
    #pragma unroll 1
    for (int ph = 0; ph < 2; ph++) {
        __syncthreads();
        stage_w(Ws, W, ph * KPH, DIM, 0, tid);
        stage_x(Xd, x, DIM, ph * KPH, row0, n, tid);
        __syncthreads();
        mma_phase(Ws, Xd, cg, rg, acc);
    }
    store_rows(g_h, DIM, acc, row0, n, cg, rg);
}

// =====================================================================
// Kernel B1: h2 = [h | maxdiff] @ W_upd + bu  (K=256 in 4 phases; gather
// fused into phase-2/3 staging with coalesced row-chunk reads).
// edge_index dtype auto-detected (int64/int32).
// =====================================================================
__global__ __launch_bounds__(TPB, 2) void k_msg1(const void* __restrict__ eidx,
        const float* __restrict__ Wu, const float* __restrict__ bu, int n) {
    extern __shared__ float sm[];
    float* Ws = sm;
    float* Xd = sm + KPH * 128;
    int* srcb = (int*)(Xd + XD_FLOATS);      // RT*KNN
    int* flag = srcb + RT * KNN;
    const int tid = threadIdx.x;
    const int cg = tid & 15, rg = tid >> 4;
    const int row0 = blockIdx.x * RT;
    if (tid == 0) {
        const long long* p64 = (const long long*)eidx;
        int ok = 1;
        #pragma unroll
        for (int i = 0; i < 16; i++) {
            long long v = p64[i];
            if (v < 0 || v >= (long long)n) ok = 0;
        }
        *flag = ok;
    }
    __syncthreads();
    const int is64 = *flag;
    for (int i = tid; i < RT * KNN; i += TPB) {
        int r = i / KNN;
        int row = row0 + r;
        int s = 0;
        if (row < n) {
            size_t e = (size_t)row * KNN + (i - r * KNN);
            long long v = is64 ? ((const long long*)eidx)[e]
                               : (long long)((const int*)eidx)[e];
            s = (int)v;
            s = min(max(s, 0), n - 1);
        }
        srcb[i] = s;
    }
    ull acc[8][4];
    acc_init(acc, bu + cg * 8);
    // phases 0-1: h half
    #pragma unroll 1
    for (int ph = 0; ph < 2; ph++) {
        __syncthreads();
        stage_w(Ws, Wu, ph * KPH, DIM, 0, tid);
        stage_x(Xd, g_h, DIM, ph * KPH, row0, n, tid);
        __syncthreads();
        mma_phase(Ws, Xd, cg, rg, acc);
    }
    // phases 2-3: maxdiff half; gather with coalesced 16B row chunks
    #pragma unroll 1
    for (int ph = 0; ph < 2; ph++) {
        __syncthreads();
        stage_w(Ws, Wu, DIM + ph * KPH, DIM, 0, tid);
        {
            const int m  = tid & 15;
            const int rp = (tid >> 4) & 1;
            const int w  = tid >> 5;
            const int d0 = ph * KPH + 4 * m;
            #pragma unroll 1
            for (int it = 0; it < 4; it++) {
                int p = (((w << 2) + it) << 1) + rp;
                int rA = 2 * p, rB = rA + 1;
                int rowA = row0 + rA, rowB = row0 + rB;
                float4 mA = make_float4(-3.4e38f, -3.4e38f, -3.4e38f, -3.4e38f);
                float4 mB = mA;
                const int* sA = srcb + rA * KNN;
                const int* sB = srcb + rB * KNN;
                #pragma unroll
                for (int j = 0; j < KNN; j++) {
                    float4 g = *(const float4*)(g_h + (size_t)sA[j] * DIM + d0);
                    mA.x = fmaxf(mA.x, g.x); mA.y = fmaxf(mA.y, g.y);
                    mA.z = fmaxf(mA.z, g.z); mA.w = fmaxf(mA.w, g.w);
                }
                #pragma unroll
                for (int j = 0; j < KNN; j++) {
                    float4 g = *(const float4*)(g_h + (size_t)sB[j] * DIM + d0);
                    mB.x = fmaxf(mB.x, g.x); mB.y = fmaxf(mB.y, g.y);
                    mB.z = fmaxf(mB.z, g.z); mB.w = fmaxf(mB.w, g.w);
                }
                float4 oA = make_float4(0.f, 0.f, 0.f, 0.f), oB = oA;
                if (rowA < n) {
                    float4 a = *(const float4*)(g_h + (size_t)rowA * DIM + d0);
                    oA.x = mA.x - a.x; oA.y = mA.y - a.y;
                    oA.z = mA.z - a.z; oA.w = mA.w - a.w;
                }
                if (rowB < n) {
                    float4 a = *(const float4*)(g_h + (size_t)rowB * DIM + d0);
                    oB.x = mB.x - a.x; oB.y = mB.y - a.y;
                    oB.z = mB.z - a.z; oB.w = mB.w - a.w;
                }
                float* xb = Xd + m * XB + 4 * p;
                ulonglong2 t;
                t.x = dup2(oA.x); t.y = dup2(oB.x); *(ulonglong2*)(xb         ) = t;
                t.x = dup2(oA.y); t.y = dup2(oB.y); *(ulonglong2*)(xb + XJ    ) = t;
                t.x = dup2(oA.z); t.y = dup2(oB.z); *(ulonglong2*)(xb + 2 * XJ) = t;
                t.x = dup2(oA.w); t.y = dup2(oB.w); *(ulonglong2*)(xb + 3 * XJ) = t;
            }
        }
        __syncthreads();
        mma_phase(Ws, Xd, cg, rg, acc);
    }
    store_rows(g_h2, DIM, acc, row0, n, cg, rg);
}

// =====================================================================
// Kernel B2: h3 = h2 @ W_out + bo; x1 = LN1(x + h3) -> g_x1
// =====================================================================
__global__ __launch_bounds__(TPB, 2) void k_msg2(const float* __restrict__ x,
        const float* __restrict__ Wo, const float* __restrict__ bo,
        const float* __restrict__ g1, const float* __restrict__ b1, int n) {
    extern __shared__ float sm[];
    float* Ws = sm;
    float* Xd = sm + KPH * 128;
    const int tid = threadIdx.x;
    const int cg = tid & 15, rg = tid >> 4;
    const int row0 = blockIdx.x * RT;
    ull acc[8][4];
    acc_init(acc, bo + cg * 8);
    #pragma unroll 1
    for (int ph = 0; ph < 2; ph++) {
        __syncthreads();
        stage_w(Ws, Wo, ph * KPH, DIM, 0, tid);
        stage_x(Xd, g_h2, DIM, ph * KPH, row0, n, tid);
        __syncthreads();
        mma_phase(Ws, Xd, cg, rg, acc);
    }
    __syncthreads();            // done with Ws/Xd; reuse smem as resid
    float* resid = sm;          // RT*DIM = 64KB
    resid_store(resid, acc, x, row0, n, cg, rg);
    __syncthreads();
    ln_rows(resid, g1, b1, g_x1, DIM, row0, n, tid);
}

// =====================================================================
// Kernel C: t = gelu(x1 @ ffn1 + b)   (grid.y = 4 col-slices of 128)
// =====================================================================
__global__ __launch_bounds__(TPB, 2) void k_ffn1(const float* __restrict__ W,
        const float* __restrict__ b, int n) {
    extern __shared__ float sm[];
    float* Ws = sm;
    float* Xd = sm + KPH * 128;
    const int tid = threadIdx.x;
    const int cg = tid & 15, rg = tid >> 4;
    const int row0 = blockIdx.x * RT;
    const int colbase = blockIdx.y * 128;
    const int c = cg * 8;
    ull acc[8][4];
    acc_init(acc, b + colbase + c);
    #pragma unroll 1
    for (int ph = 0; ph < 2; ph++) {
        __syncthreads();
        stage_w(Ws, W, ph * KPH, FFN, colbase, tid);
        stage_x(Xd, g_x1, DIM, ph * KPH, row0, n, tid);
        __syncthreads();
        mma_phase(Ws, Xd, cg, rg, acc);
    }
    #pragma unroll
    for (int r = 0; r < 8; r++) {
        int row = row0 + rg * 8 + r;
        if (row < n) {
            float4 f0, f1;
            f0.x = gelu_exact(lo2(acc[r][0])); f0.y = gelu_exact(hi2(acc[r][0]));
            f0.z = gelu_exact(lo2(acc[r][1])); f0.w = gelu_exact(hi2(acc[r][1]));
            f1.x = gelu_exact(lo2(acc[r][2])); f1.y = gelu_exact(hi2(acc[r][2]));
            f1.z = gelu_exact(lo2(acc[r][3])); f1.w = gelu_exact(hi2(acc[r][3]));
            *(float4*)(g_t + (size_t)row * FFN + colbase + c) = f0;
            *(float4*)(g_t + (size_t)row * FFN + colbase + c + 4) = f1;
        }
    }
}

// =====================================================================
// Kernel D: f = t @ ffn2 + b2; out = LN2(x1 + f)   (K=512 in 8 phases)
// =====================================================================
__global__ __launch_bounds__(TPB, 2) void k_ffn2(const float* __restrict__ W,
        const float* __restrict__ b2, const float* __restrict__ g2,
        const float* __restrict__ bl, float* __restrict__ out, int n) {
    extern __shared__ float sm[];
    float* Ws = sm;
    float* Xd = sm + KPH * 128;
    const int tid = threadIdx.x;
    const int cg = tid & 15, rg = tid >> 4;
    const int row0 = blockIdx.x * RT;
    ull acc[8][4];
    acc_init(acc, b2 + cg * 8);
    #pragma unroll 1
    for (int ph = 0; ph < 8; ph++) {
        __syncthreads();
        stage_w(Ws, W, ph * KPH, DIM, 0, tid);
        stage_x(Xd, g_t, FFN, ph * KPH, row0, n, tid);
        __syncthreads();
        mma_phase(Ws, Xd, cg, rg, acc);
    }
    __syncthreads();            // reuse smem as resid
    float* resid = sm;
    resid_store(resid, acc, g_x1, row0, n, cg, rg);
    __syncthreads();
    ln_rows(resid, g2, bl, out, DIM, row0, n, tid);
}

// =====================================================================
extern "C" void kernel_launch(void* const* d_in, const int* in_sizes, int n_in,
                              void* d_out, int out_size) {
    const float* x    = (const float*)d_in[0];
    const void*  ei   = (const void*)d_in[1];   // edge_index [2,E]; row 0 = src
    const float* Winw = (const float*)d_in[2];
    const float* Winb = (const float*)d_in[3];
    const float* Wupw = (const float*)d_in[4];
    const float* Wupb = (const float*)d_in[5];
    const float* Wouw = (const float*)d_in[6];
    const float* Woub = (const float*)d_in[7];
    const float* ln1g = (const float*)d_in[8];
    const float* ln1b = (const float*)d_in[9];
    const float* ln2g = (const float*)d_in[10];
    const float* ln2b = (const float*)d_in[11];
    const float* f1w  = (const float*)d_in[12];
    const float* f1b  = (const float*)d_in[13];
    const float* f2w  = (const float*)d_in[14];
    const float* f2b  = (const float*)d_in[15];
    float* out = (float*)d_out;

    const int n = in_sizes[0] / DIM;

    const int SMEM_GEMM = (KPH * 128 + XD_FLOATS) * 4;                 // ~97.3 KB
    const int SMEM_MSG1 = SMEM_GEMM + (RT * KNN + 1) * 4;              // +4.6 KB

    cudaFuncSetAttribute(k_win,  cudaFuncAttributeMaxDynamicSharedMemorySize, SMEM_GEMM);
    cudaFuncSetAttribute(k_msg1, cudaFuncAttributeMaxDynamicSharedMemorySize, SMEM_MSG1);
    cudaFuncSetAttribute(k_msg2, cudaFuncAttributeMaxDynamicSharedMemorySize, SMEM_GEMM);
    cudaFuncSetAttribute(k_ffn1, cudaFuncAttributeMaxDynamicSharedMemorySize, SMEM_GEMM);
    cudaFuncSetAttribute(k_ffn2, cudaFuncAttributeMaxDynamicSharedMemorySize, SMEM_GEMM);

    const int nb = (n + RT - 1) / RT;
    dim3 gc(nb, 4);

    k_win <<<nb, TPB, SMEM_GEMM>>>(x, Winw, Winb, n);
    k_msg1<<<nb, TPB, SMEM_MSG1>>>(ei, Wupw, Wupb, n);
    k_msg2<<<nb, TPB, SMEM_GEMM>>>(x, Wouw, Woub, ln1g, ln1b, n);
    k_ffn1<<<gc, TPB, SMEM_GEMM>>>(f1w, f1b, n);
    k_ffn2<<<nb, TPB, SMEM_GEMM>>>(f2w, f2b, ln2g, ln2b, out, n);
}